// round 1
// baseline (speedup 1.0000x reference)
#include <cuda_runtime.h>
#include <cuda_bf16.h>

// Problem constants
#define L_LAYERS 2
#define U_DIM    256
#define NL_LAB   64
#define B_DIM    128
#define T_DIM    128
#define DEG      5
#define BT       (B_DIM * T_DIM)          // 16384 nodes
#define E_EDGES  (BT * DEG)               // 81920

// ---------------------------------------------------------------------------
// Scratch (device globals — no allocation allowed)
// ---------------------------------------------------------------------------
__device__ float g_X0[BT * U_DIM];        // node features ping
__device__ float g_X1[BT * U_DIM];        // node features pong
__device__ float g_XVin[BT * U_DIM];      // X @ V_in
__device__ float g_XVout[BT * U_DIM];     // X @ V_out
__device__ float g_XVloop[BT * U_DIM];    // X @ W_loop
__device__ float g_gin[BT];
__device__ float g_gout[BT];
__device__ float g_gloop[BT];
__device__ float g_enc[B_DIM * U_DIM];

// ---------------------------------------------------------------------------
// 1) Embedding gather: X[n=b*T+t, u] = emb[src[t,b], u]
// ---------------------------------------------------------------------------
__global__ void embed_k(const int* __restrict__ src,
                        const float* __restrict__ emb,
                        float* __restrict__ X)
{
    int n = blockIdx.x;                       // node = b*T + t
    int b = n / T_DIM, t = n % T_DIM;
    int tok = src[t * B_DIM + b];
    int u = threadIdx.x;
    X[n * U_DIM + u] = emb[tok * U_DIM + u];
}

// ---------------------------------------------------------------------------
// 2) SGEMM: C = A[M=16384,K=256] * W[K=256,N=256] row-major.
//    One launch computes all three weight matrices (in/out/loop) via
//    blockIdx.y in [0,6): sel = y/2 picks W, (y&1)*128 picks N half.
//    128x128 block tile, 8x8 thread tile, BK=8, 256 threads.
// ---------------------------------------------------------------------------
#define BM 128
#define BN 128
#define BKK 8
#define TM 8
#define TN 8

__global__ __launch_bounds__(256, 2)
void gemm3_k(const float* __restrict__ A,
             const float* __restrict__ W0, const float* __restrict__ W1,
             const float* __restrict__ W2,
             float* __restrict__ C0, float* __restrict__ C1,
             float* __restrict__ C2)
{
    const int sel     = blockIdx.y >> 1;
    const int colbase = (blockIdx.y & 1) * BN;
    const float* __restrict__ W = (sel == 0) ? W0 : ((sel == 1) ? W1 : W2);
    float* __restrict__ C       = (sel == 0) ? C0 : ((sel == 1) ? C1 : C2);
    const int mbase = blockIdx.x * BM;

    __shared__ __align__(16) float As[BKK][BM];   // transposed A tile
    __shared__ __align__(16) float Bs[BKK][BN];

    const int tid  = threadIdx.x;                 // 0..255
    const int tcol = tid & 15;                    // 0..15 (N direction)
    const int trow = tid >> 4;                    // 0..15 (M direction)

    // A tile load mapping: BM x BKK = 1024 floats, one float4 per thread.
    const int aRow  = tid >> 1;                   // 0..127
    const int aCol4 = (tid & 1) * 4;              // 0 or 4
    // B tile load mapping: BKK x BN = 1024 floats, one float4 per thread.
    const int bRow  = tid >> 5;                   // 0..7
    const int bCol4 = (tid & 31) * 4;             // 0..124

    float acc[TM][TN];
#pragma unroll
    for (int i = 0; i < TM; i++)
#pragma unroll
        for (int j = 0; j < TN; j++) acc[i][j] = 0.f;

    for (int k0 = 0; k0 < U_DIM; k0 += BKK) {
        float4 av = *reinterpret_cast<const float4*>(
            &A[(size_t)(mbase + aRow) * U_DIM + k0 + aCol4]);
        As[aCol4 + 0][aRow] = av.x;
        As[aCol4 + 1][aRow] = av.y;
        As[aCol4 + 2][aRow] = av.z;
        As[aCol4 + 3][aRow] = av.w;
        float4 bv = *reinterpret_cast<const float4*>(
            &W[(size_t)(k0 + bRow) * U_DIM + colbase + bCol4]);
        *reinterpret_cast<float4*>(&Bs[bRow][bCol4]) = bv;
        __syncthreads();

#pragma unroll
        for (int kk = 0; kk < BKK; kk++) {
            float4 m0 = *reinterpret_cast<const float4*>(&As[kk][trow * TM]);
            float4 m1 = *reinterpret_cast<const float4*>(&As[kk][trow * TM + 4]);
            float4 n0 = *reinterpret_cast<const float4*>(&Bs[kk][tcol * TN]);
            float4 n1 = *reinterpret_cast<const float4*>(&Bs[kk][tcol * TN + 4]);
            float regM[TM] = {m0.x, m0.y, m0.z, m0.w, m1.x, m1.y, m1.z, m1.w};
            float regN[TN] = {n0.x, n0.y, n0.z, n0.w, n1.x, n1.y, n1.z, n1.w};
#pragma unroll
            for (int i = 0; i < TM; i++)
#pragma unroll
                for (int j = 0; j < TN; j++)
                    acc[i][j] = fmaf(regM[i], regN[j], acc[i][j]);
        }
        __syncthreads();
    }

#pragma unroll
    for (int i = 0; i < TM; i++) {
        int m = mbase + trow * TM + i;
        float4 v0 = make_float4(acc[i][0], acc[i][1], acc[i][2], acc[i][3]);
        float4 v1 = make_float4(acc[i][4], acc[i][5], acc[i][6], acc[i][7]);
        *reinterpret_cast<float4*>(&C[(size_t)m * U_DIM + colbase + tcol * TN])     = v0;
        *reinterpret_cast<float4*>(&C[(size_t)m * U_DIM + colbase + tcol * TN + 4]) = v1;
    }
}

// ---------------------------------------------------------------------------
// 3) Gates: gin[n]=X[n]·Vg_in, gout[n]=X[n]·Vg_out, gloop[n]=X[n]·Wg_loop.
//    One warp per node.
// ---------------------------------------------------------------------------
__global__ void gate_k(const float* __restrict__ X,
                       const float* __restrict__ vgin,
                       const float* __restrict__ vgout,
                       const float* __restrict__ wgl,
                       float* __restrict__ gin, float* __restrict__ gout,
                       float* __restrict__ gloop)
{
    int n    = blockIdx.x * 8 + (threadIdx.x >> 5);
    int lane = threadIdx.x & 31;
    const float* xr = X + (size_t)n * U_DIM;
    float s0 = 0.f, s1 = 0.f, s2 = 0.f;
#pragma unroll
    for (int k = lane; k < U_DIM; k += 32) {
        float x = xr[k];
        s0 = fmaf(x, vgin[k], s0);
        s1 = fmaf(x, vgout[k], s1);
        s2 = fmaf(x, wgl[k], s2);
    }
#pragma unroll
    for (int off = 16; off > 0; off >>= 1) {
        s0 += __shfl_down_sync(0xffffffffu, s0, off);
        s1 += __shfl_down_sync(0xffffffffu, s1, off);
        s2 += __shfl_down_sync(0xffffffffu, s2, off);
    }
    if (lane == 0) { gin[n] = s0; gout[n] = s1; gloop[n] = s2; }
}

// ---------------------------------------------------------------------------
// 4) Edge aggregation: one block per node, 256 threads over u.
//    out[n,u] = relu( sum_d p_in*(XVin[src]+b_in[lab]) +
//                     sum_d p_out*(XVout[src]+b_out[lab]) +
//                     p_loop*XVloop[n] ) * sent_mask
// ---------------------------------------------------------------------------
__global__ void agg_k(const float* __restrict__ XVin,
                      const float* __restrict__ XVout,
                      const float* __restrict__ XVloop,
                      const float* __restrict__ gin,
                      const float* __restrict__ gout,
                      const float* __restrict__ gloop,
                      const int* __restrict__ arc_in,   // [2,E]
                      const int* __restrict__ arc_out,  // [2,E]
                      const int* __restrict__ lab_in,
                      const int* __restrict__ lab_out,
                      const float* __restrict__ b_in,   // [NL,U] for this layer
                      const float* __restrict__ bg_in,  // [NL]
                      const float* __restrict__ b_out,
                      const float* __restrict__ bg_out,
                      const float* __restrict__ mask_in,   // [BT,DEG]
                      const float* __restrict__ mask_out,
                      const float* __restrict__ mask_loop, // [BT]
                      const float* __restrict__ sent_mask, // [T,B]
                      float* __restrict__ Y)
{
    int n = blockIdx.x;
    int u = threadIdx.x;

    __shared__ float p_in[DEG], p_out[DEG], p_loop;
    __shared__ int   s_in[DEG], s_out[DEG], l_in[DEG], l_out[DEG];

    if (u < DEG) {
        int d = u;
        int e = n * DEG + d;
        int si = arc_in[e] * T_DIM + arc_in[E_EDGES + e];
        int li = lab_in[e];
        float gi = gin[si] + bg_in[li];
        p_in[d] = (1.f / (1.f + __expf(-gi))) * mask_in[n * DEG + d];
        s_in[d] = si; l_in[d] = li;

        int so = arc_out[e] * T_DIM + arc_out[E_EDGES + e];
        int lo = lab_out[e];
        float go = gout[so] + bg_out[lo];
        p_out[d] = (1.f / (1.f + __expf(-go))) * mask_out[n * DEG + d];
        s_out[d] = so; l_out[d] = lo;
    }
    if (u == DEG) {
        float gl = gloop[n];
        p_loop = (1.f / (1.f + __expf(-gl))) * mask_loop[n];
    }
    __syncthreads();

    float acc = p_loop * XVloop[(size_t)n * U_DIM + u];
#pragma unroll
    for (int d = 0; d < DEG; d++) {
        acc = fmaf(p_in[d],
                   XVin[(size_t)s_in[d] * U_DIM + u] + b_in[l_in[d] * U_DIM + u],
                   acc);
        acc = fmaf(p_out[d],
                   XVout[(size_t)s_out[d] * U_DIM + u] + b_out[l_out[d] * U_DIM + u],
                   acc);
    }
    acc = fmaxf(acc, 0.f);
    int b = n / T_DIM, t = n % T_DIM;
    Y[(size_t)n * U_DIM + u] = acc * sent_mask[t * B_DIM + b];
}

// ---------------------------------------------------------------------------
// 5) enc[b,u] = (sum_t X[b*T+t,u]) / (sum_t sent_mask[t,b])
// ---------------------------------------------------------------------------
__global__ void enc_k(const float* __restrict__ X,
                      const float* __restrict__ sent_mask,
                      float* __restrict__ enc)
{
    int b = blockIdx.x;
    int u = threadIdx.x;
    float s = 0.f;
#pragma unroll 4
    for (int t = 0; t < T_DIM; t++)
        s += X[((size_t)b * T_DIM + t) * U_DIM + u];
    __shared__ float ms;
    if (u == 0) {
        float m = 0.f;
        for (int t = 0; t < T_DIM; t++) m += sent_mask[t * B_DIM + b];
        ms = m;
    }
    __syncthreads();
    enc[b * U_DIM + u] = s / ms;
}

// ---------------------------------------------------------------------------
// 6) h_all[k,b,w] = sum_u enc[b,u] * H[k,u,w] -> d_out[0 .. 4*B*U)
// ---------------------------------------------------------------------------
__global__ void hall_k(const float* __restrict__ enc,
                       const float* __restrict__ H,
                       float* __restrict__ out)
{
    int k = blockIdx.y;   // 0..3
    int b = blockIdx.x;   // 0..127
    int w = threadIdx.x;  // 0..255
    __shared__ float es[U_DIM];
    es[w] = enc[b * U_DIM + w];
    __syncthreads();
    const float* Hk = H + (size_t)k * U_DIM * U_DIM;
    float acc = 0.f;
#pragma unroll 8
    for (int u = 0; u < U_DIM; u++)
        acc = fmaf(es[u], Hk[u * U_DIM + w], acc);
    out[((size_t)k * B_DIM + b) * U_DIM + w] = acc;
}

// ---------------------------------------------------------------------------
// 7) memory_bank[t,b,u] = X[b*T+t, u] -> d_out[4*B*U ..)
// ---------------------------------------------------------------------------
__global__ void membank_k(const float* __restrict__ X, float* __restrict__ out)
{
    int n = blockIdx.x;  // b*T + t
    int u = threadIdx.x;
    int b = n / T_DIM, t = n % T_DIM;
    out[((size_t)t * B_DIM + b) * U_DIM + u] = X[(size_t)n * U_DIM + u];
}

// ---------------------------------------------------------------------------
// Launch
// ---------------------------------------------------------------------------
extern "C" void kernel_launch(void* const* d_in, const int* in_sizes, int n_in,
                              void* d_out, int out_size)
{
    const int*   src       = (const int*)  d_in[0];
    const int*   arc_in    = (const int*)  d_in[1];
    const int*   arc_out   = (const int*)  d_in[2];
    const int*   lab_in    = (const int*)  d_in[3];
    const int*   lab_out   = (const int*)  d_in[4];
    const float* mask_in   = (const float*)d_in[5];
    const float* mask_out  = (const float*)d_in[6];
    const float* mask_loop = (const float*)d_in[7];
    const float* sent_mask = (const float*)d_in[8];
    const float* emb       = (const float*)d_in[9];
    const float* V_in      = (const float*)d_in[10];
    const float* b_in      = (const float*)d_in[11];
    const float* Vg_in     = (const float*)d_in[12];
    const float* bg_in     = (const float*)d_in[13];
    const float* V_out     = (const float*)d_in[14];
    const float* b_out     = (const float*)d_in[15];
    const float* Vg_out    = (const float*)d_in[16];
    const float* bg_out    = (const float*)d_in[17];
    const float* W_loop    = (const float*)d_in[18];
    const float* Wg_loop   = (const float*)d_in[19];
    const float* H         = (const float*)d_in[20];
    float* out = (float*)d_out;

    float *pX0, *pX1, *pXVin, *pXVout, *pXVloop, *pgin, *pgout, *pgloop, *penc;
    cudaGetSymbolAddress((void**)&pX0,     g_X0);
    cudaGetSymbolAddress((void**)&pX1,     g_X1);
    cudaGetSymbolAddress((void**)&pXVin,   g_XVin);
    cudaGetSymbolAddress((void**)&pXVout,  g_XVout);
    cudaGetSymbolAddress((void**)&pXVloop, g_XVloop);
    cudaGetSymbolAddress((void**)&pgin,    g_gin);
    cudaGetSymbolAddress((void**)&pgout,   g_gout);
    cudaGetSymbolAddress((void**)&pgloop,  g_gloop);
    cudaGetSymbolAddress((void**)&penc,    g_enc);

    embed_k<<<BT, U_DIM>>>(src, emb, pX0);

    float* Xcur = pX0;
    float* Xnxt = pX1;
    for (int l = 0; l < L_LAYERS; l++) {
        const size_t wOff  = (size_t)l * U_DIM * U_DIM;  // V matrices
        const size_t gOff  = (size_t)l * U_DIM;          // Vg vectors
        const size_t bOff  = (size_t)l * NL_LAB * U_DIM; // label bias
        const size_t bgOff = (size_t)l * NL_LAB;         // label gate bias

        dim3 ggrid(BT / BM, 6);
        gemm3_k<<<ggrid, 256>>>(Xcur,
                                V_in + wOff, V_out + wOff, W_loop + wOff,
                                pXVin, pXVout, pXVloop);
        gate_k<<<BT / 8, 256>>>(Xcur, Vg_in + gOff, Vg_out + gOff,
                                Wg_loop + gOff, pgin, pgout, pgloop);
        agg_k<<<BT, U_DIM>>>(pXVin, pXVout, pXVloop, pgin, pgout, pgloop,
                             arc_in, arc_out, lab_in, lab_out,
                             b_in + bOff, bg_in + bgOff,
                             b_out + bOff, bg_out + bgOff,
                             mask_in, mask_out, mask_loop, sent_mask, Xnxt);
        float* tmp = Xcur; Xcur = Xnxt; Xnxt = tmp;
    }

    // Xcur now holds the final memory_bank (node-major layout).
    enc_k<<<B_DIM, U_DIM>>>(Xcur, sent_mask, penc);
    hall_k<<<dim3(B_DIM, 4), U_DIM>>>(penc, H, out);
    membank_k<<<BT, U_DIM>>>(Xcur, out + 4 * B_DIM * U_DIM);
}

// round 2
// speedup vs baseline: 2.4262x; 2.4262x over previous
#include <cuda_runtime.h>
#include <cuda_bf16.h>
#include <cstdint>

// Problem constants
#define L_LAYERS 2
#define U_DIM    256
#define U4       (U_DIM / 4)
#define NL_LAB   64
#define B_DIM    128
#define T_DIM    128
#define DEG      5
#define BT       (B_DIM * T_DIM)          // 16384 nodes
#define E_EDGES  (BT * DEG)               // 81920

// ---------------------------------------------------------------------------
// Scratch (device globals — no allocation allowed)
// ---------------------------------------------------------------------------
__device__ float g_X0[BT * U_DIM];
__device__ float g_X1[BT * U_DIM];
__device__ float g_XVin[BT * U_DIM];
__device__ float g_XVout[BT * U_DIM];
__device__ float g_XVloop[BT * U_DIM];
__device__ float g_gin[BT];
__device__ float g_gout[BT];
__device__ float g_gloop[BT];
__device__ float g_enc[B_DIM * U_DIM];

// ---------------------------------------------------------------------------
// helpers
// ---------------------------------------------------------------------------
__device__ __forceinline__ uint32_t f2tf32(float f) {
    uint32_t r;
    asm("cvt.rna.tf32.f32 %0, %1;" : "=r"(r) : "f"(f));
    return r;
}

__device__ __forceinline__ void mma_tf32(float* d, const uint32_t* a,
                                         const uint32_t* b) {
    asm volatile(
        "mma.sync.aligned.m16n8k8.row.col.f32.tf32.tf32.f32 "
        "{%0,%1,%2,%3}, {%4,%5,%6,%7}, {%8,%9}, {%0,%1,%2,%3};\n"
        : "+f"(d[0]), "+f"(d[1]), "+f"(d[2]), "+f"(d[3])
        : "r"(a[0]), "r"(a[1]), "r"(a[2]), "r"(a[3]), "r"(b[0]), "r"(b[1]));
}

// ---------------------------------------------------------------------------
// 1) Embedding gather (float4): X[n=b*T+t] = emb[src[t,b]]
// ---------------------------------------------------------------------------
__global__ void embed_k(const int* __restrict__ src,
                        const float* __restrict__ emb,
                        float* __restrict__ X)
{
    int grp = threadIdx.x >> 6;               // node within block
    int n   = blockIdx.x * 4 + grp;
    int lu  = threadIdx.x & 63;
    int b = n / T_DIM, t = n % T_DIM;
    int tok = src[t * B_DIM + b];
    reinterpret_cast<float4*>(X)[(size_t)n * U4 + lu] =
        reinterpret_cast<const float4*>(emb)[(size_t)tok * U4 + lu];
}

// ---------------------------------------------------------------------------
// 2) TF32 tensor-core GEMM: C = A[16384,256] * W[256,256].
//    blockIdx.y in [0,6): sel=y>>1 picks W/C, (y&1)*128 picks N half.
//    Block tile 128x128, BK=16, 8 warps (4 in M x 2 in N), warp tile 32x64.
// ---------------------------------------------------------------------------
#define GBM 128
#define GBN 128
#define GBK 16

__global__ __launch_bounds__(256)
void gemm3_tf32_k(const float* __restrict__ A,
                  const float* __restrict__ W0, const float* __restrict__ W1,
                  const float* __restrict__ W2,
                  float* __restrict__ C0, float* __restrict__ C1,
                  float* __restrict__ C2)
{
    const int sel     = blockIdx.y >> 1;
    const int colbase = (blockIdx.y & 1) * GBN;
    const float* __restrict__ W = (sel == 0) ? W0 : ((sel == 1) ? W1 : W2);
    float* __restrict__ C       = (sel == 0) ? C0 : ((sel == 1) ? C1 : C2);
    const int mbase = blockIdx.x * GBM;

    // As[m][k] pad->20 : fragment loads conflict-free (banks 20g+t distinct)
    // Bs[k][n] pad->136: fragment loads conflict-free (banks 8t+g distinct)
    __shared__ __align__(16) uint32_t As[GBM][GBK + 4];
    __shared__ __align__(16) uint32_t Bs[GBK][GBN + 8];

    const int tid  = threadIdx.x;
    const int lane = tid & 31;
    const int warp = tid >> 5;
    const int wm   = (warp & 3) * 32;          // warp M offset
    const int wn   = (warp >> 2) * 64;         // warp N offset
    const int g    = lane >> 2;                // 0..7
    const int t    = lane & 3;                 // 0..3

    // global->smem mappings
    const int aRow = tid >> 1;                 // 0..127
    const int aK   = (tid & 1) * 8;            // 0 or 8
    const int bK   = tid >> 4;                 // 0..15
    const int bN   = (tid & 15) * 4;           // 0..60

    float acc[2][8][4];
#pragma unroll
    for (int mi = 0; mi < 2; mi++)
#pragma unroll
        for (int ni = 0; ni < 8; ni++)
#pragma unroll
            for (int c = 0; c < 4; c++) acc[mi][ni][c] = 0.f;

    const float* Aptr = A + (size_t)(mbase + aRow) * U_DIM + aK;
    const float* Wptr = W + (size_t)bK * U_DIM + colbase + bN;

    // prologue loads
    float4 av0 = *reinterpret_cast<const float4*>(Aptr);
    float4 av1 = *reinterpret_cast<const float4*>(Aptr + 4);
    float4 bv0 = *reinterpret_cast<const float4*>(Wptr);
    float4 bv1 = *reinterpret_cast<const float4*>(Wptr + 64);

    for (int k0 = 0; k0 < U_DIM; k0 += GBK) {
        __syncthreads();   // previous compute done before overwrite
        {
            uint4 u;
            u.x = f2tf32(av0.x); u.y = f2tf32(av0.y);
            u.z = f2tf32(av0.z); u.w = f2tf32(av0.w);
            *reinterpret_cast<uint4*>(&As[aRow][aK]) = u;
            u.x = f2tf32(av1.x); u.y = f2tf32(av1.y);
            u.z = f2tf32(av1.z); u.w = f2tf32(av1.w);
            *reinterpret_cast<uint4*>(&As[aRow][aK + 4]) = u;
            u.x = f2tf32(bv0.x); u.y = f2tf32(bv0.y);
            u.z = f2tf32(bv0.z); u.w = f2tf32(bv0.w);
            *reinterpret_cast<uint4*>(&Bs[bK][bN]) = u;
            u.x = f2tf32(bv1.x); u.y = f2tf32(bv1.y);
            u.z = f2tf32(bv1.z); u.w = f2tf32(bv1.w);
            *reinterpret_cast<uint4*>(&Bs[bK][bN + 64]) = u;
        }
        __syncthreads();

        if (k0 + GBK < U_DIM) {   // prefetch next tile into registers
            av0 = *reinterpret_cast<const float4*>(Aptr + k0 + GBK);
            av1 = *reinterpret_cast<const float4*>(Aptr + k0 + GBK + 4);
            bv0 = *reinterpret_cast<const float4*>(Wptr + (size_t)GBK * U_DIM * ((k0 / GBK) + 1) - (size_t)GBK * U_DIM * (k0 / GBK) + (size_t)(k0) * U_DIM + (size_t)GBK * U_DIM - (size_t)k0 * U_DIM);
        }
        // NOTE: pointer arithmetic above simplified below (recomputed cleanly)
        if (k0 + GBK < U_DIM) {
            const float* Wnext = W + (size_t)(k0 + GBK + bK) * U_DIM + colbase + bN;
            bv0 = *reinterpret_cast<const float4*>(Wnext);
            bv1 = *reinterpret_cast<const float4*>(Wnext + 64);
        }

#pragma unroll
        for (int ks = 0; ks < GBK; ks += 8) {
            uint32_t afr[2][4];
#pragma unroll
            for (int mi = 0; mi < 2; mi++) {
                int m0 = wm + mi * 16;
                afr[mi][0] = As[m0 + g][ks + t];
                afr[mi][1] = As[m0 + g + 8][ks + t];
                afr[mi][2] = As[m0 + g][ks + t + 4];
                afr[mi][3] = As[m0 + g + 8][ks + t + 4];
            }
            uint32_t bfr[8][2];
#pragma unroll
            for (int ni = 0; ni < 8; ni++) {
                int n0 = wn + ni * 8 + g;
                bfr[ni][0] = Bs[ks + t][n0];
                bfr[ni][1] = Bs[ks + t + 4][n0];
            }
#pragma unroll
            for (int mi = 0; mi < 2; mi++)
#pragma unroll
                for (int ni = 0; ni < 8; ni++)
                    mma_tf32(acc[mi][ni], afr[mi], bfr[ni]);
        }
    }

    // epilogue: c0,c1 = (row g, cols 2t,2t+1); c2,c3 = (row g+8, same cols)
#pragma unroll
    for (int mi = 0; mi < 2; mi++) {
#pragma unroll
        for (int ni = 0; ni < 8; ni++) {
            int row = mbase + wm + mi * 16 + g;
            int col = colbase + wn + ni * 8 + 2 * t;
            float2 v0 = make_float2(acc[mi][ni][0], acc[mi][ni][1]);
            float2 v1 = make_float2(acc[mi][ni][2], acc[mi][ni][3]);
            *reinterpret_cast<float2*>(&C[(size_t)row * U_DIM + col])       = v0;
            *reinterpret_cast<float2*>(&C[(size_t)(row + 8) * U_DIM + col]) = v1;
        }
    }
}

// ---------------------------------------------------------------------------
// 3) Gates: one warp per node, 3 dot products.
// ---------------------------------------------------------------------------
__global__ void gate_k(const float* __restrict__ X,
                       const float* __restrict__ vgin,
                       const float* __restrict__ vgout,
                       const float* __restrict__ wgl,
                       float* __restrict__ gin, float* __restrict__ gout,
                       float* __restrict__ gloop)
{
    int n    = blockIdx.x * 8 + (threadIdx.x >> 5);
    int lane = threadIdx.x & 31;
    const float4* xr = reinterpret_cast<const float4*>(X + (size_t)n * U_DIM);
    const float4* v0 = reinterpret_cast<const float4*>(vgin);
    const float4* v1 = reinterpret_cast<const float4*>(vgout);
    const float4* v2 = reinterpret_cast<const float4*>(wgl);
    float s0 = 0.f, s1 = 0.f, s2 = 0.f;
#pragma unroll
    for (int k = lane; k < U4; k += 32) {
        float4 x = xr[k];
        float4 a = v0[k], b = v1[k], c = v2[k];
        s0 += x.x * a.x + x.y * a.y + x.z * a.z + x.w * a.w;
        s1 += x.x * b.x + x.y * b.y + x.z * b.z + x.w * b.w;
        s2 += x.x * c.x + x.y * c.y + x.z * c.z + x.w * c.w;
    }
#pragma unroll
    for (int off = 16; off > 0; off >>= 1) {
        s0 += __shfl_down_sync(0xffffffffu, s0, off);
        s1 += __shfl_down_sync(0xffffffffu, s1, off);
        s2 += __shfl_down_sync(0xffffffffu, s2, off);
    }
    if (lane == 0) { gin[n] = s0; gout[n] = s1; gloop[n] = s2; }
}

// ---------------------------------------------------------------------------
// 4) Edge aggregation, float4: 64 threads/node, 4 nodes/block.
// ---------------------------------------------------------------------------
__global__ __launch_bounds__(256)
void agg_k(const float* __restrict__ XVin,
           const float* __restrict__ XVout,
           const float* __restrict__ XVloop,
           const float* __restrict__ gin,
           const float* __restrict__ gout,
           const float* __restrict__ gloop,
           const int* __restrict__ arc_in,
           const int* __restrict__ arc_out,
           const int* __restrict__ lab_in,
           const int* __restrict__ lab_out,
           const float* __restrict__ b_in,    // [NL,U] this layer
           const float* __restrict__ bg_in,   // [NL]
           const float* __restrict__ b_out,
           const float* __restrict__ bg_out,
           const float* __restrict__ mask_in,
           const float* __restrict__ mask_out,
           const float* __restrict__ mask_loop,
           const float* __restrict__ sent_mask,
           float* __restrict__ Y)
{
    int grp = threadIdx.x >> 6;      // node within block (0..3)
    int n   = blockIdx.x * 4 + grp;
    int lu  = threadIdx.x & 63;      // float4 lane over U

    __shared__ float p_in[4][DEG], p_out[4][DEG], p_loop[4];
    __shared__ int   s_in[4][DEG], s_out[4][DEG], l_in[4][DEG], l_out[4][DEG];

    if (lu < DEG) {
        int d = lu, e = n * DEG + d;
        int si = arc_in[e] * T_DIM + arc_in[E_EDGES + e];
        int li = lab_in[e];
        float gi = gin[si] + bg_in[li];
        p_in[grp][d] = (1.f / (1.f + __expf(-gi))) * mask_in[n * DEG + d];
        s_in[grp][d] = si; l_in[grp][d] = li;
    } else if (lu < 2 * DEG) {
        int d = lu - DEG, e = n * DEG + d;
        int so = arc_out[e] * T_DIM + arc_out[E_EDGES + e];
        int lo = lab_out[e];
        float go = gout[so] + bg_out[lo];
        p_out[grp][d] = (1.f / (1.f + __expf(-go))) * mask_out[n * DEG + d];
        s_out[grp][d] = so; l_out[grp][d] = lo;
    } else if (lu == 2 * DEG) {
        p_loop[grp] = (1.f / (1.f + __expf(-gloop[n]))) * mask_loop[n];
    }
    __syncthreads();

    const float4* XVin4   = reinterpret_cast<const float4*>(XVin);
    const float4* XVout4  = reinterpret_cast<const float4*>(XVout);
    const float4* XVloop4 = reinterpret_cast<const float4*>(XVloop);
    const float4* bin4    = reinterpret_cast<const float4*>(b_in);
    const float4* bout4   = reinterpret_cast<const float4*>(b_out);

    float pl = p_loop[grp];
    float4 h = XVloop4[(size_t)n * U4 + lu];
    float4 acc = make_float4(pl * h.x, pl * h.y, pl * h.z, pl * h.w);

#pragma unroll
    for (int d = 0; d < DEG; d++) {
        float p = p_in[grp][d];
        float4 v = XVin4[(size_t)s_in[grp][d] * U4 + lu];
        float4 bb = bin4[(size_t)l_in[grp][d] * U4 + lu];
        acc.x = fmaf(p, v.x + bb.x, acc.x);
        acc.y = fmaf(p, v.y + bb.y, acc.y);
        acc.z = fmaf(p, v.z + bb.z, acc.z);
        acc.w = fmaf(p, v.w + bb.w, acc.w);
        p = p_out[grp][d];
        v = XVout4[(size_t)s_out[grp][d] * U4 + lu];
        bb = bout4[(size_t)l_out[grp][d] * U4 + lu];
        acc.x = fmaf(p, v.x + bb.x, acc.x);
        acc.y = fmaf(p, v.y + bb.y, acc.y);
        acc.z = fmaf(p, v.z + bb.z, acc.z);
        acc.w = fmaf(p, v.w + bb.w, acc.w);
    }
    int b = n / T_DIM, t = n % T_DIM;
    float sm = sent_mask[t * B_DIM + b];
    acc.x = fmaxf(acc.x, 0.f) * sm;
    acc.y = fmaxf(acc.y, 0.f) * sm;
    acc.z = fmaxf(acc.z, 0.f) * sm;
    acc.w = fmaxf(acc.w, 0.f) * sm;
    reinterpret_cast<float4*>(Y)[(size_t)n * U4 + lu] = acc;
}

// ---------------------------------------------------------------------------
// 5) enc[b] = (sum_t X[b*T+t]) / (sum_t sent_mask[t,b])   (float4)
// ---------------------------------------------------------------------------
__global__ void enc_k(const float* __restrict__ X,
                      const float* __restrict__ sent_mask,
                      float* __restrict__ enc)
{
    int b = blockIdx.x;
    int u = threadIdx.x;  // 0..63
    const float4* X4 = reinterpret_cast<const float4*>(X);
    float4 s = make_float4(0.f, 0.f, 0.f, 0.f);
#pragma unroll 4
    for (int t = 0; t < T_DIM; t++) {
        float4 v = X4[((size_t)b * T_DIM + t) * U4 + u];
        s.x += v.x; s.y += v.y; s.z += v.z; s.w += v.w;
    }
    __shared__ float ms;
    if (u == 0) {
        float m = 0.f;
        for (int t = 0; t < T_DIM; t++) m += sent_mask[t * B_DIM + b];
        ms = m;
    }
    __syncthreads();
    float inv = 1.f / ms;
    s.x *= inv; s.y *= inv; s.z *= inv; s.w *= inv;
    reinterpret_cast<float4*>(enc)[b * U4 + u] = s;
}

// ---------------------------------------------------------------------------
// 6) h_all[k,b,w] = sum_u enc[b,u] * H[k,u,w]
// ---------------------------------------------------------------------------
__global__ void hall_k(const float* __restrict__ enc,
                       const float* __restrict__ H,
                       float* __restrict__ out)
{
    int k = blockIdx.y, b = blockIdx.x, w = threadIdx.x;
    __shared__ float es[U_DIM];
    es[w] = enc[b * U_DIM + w];
    __syncthreads();
    const float* Hk = H + (size_t)k * U_DIM * U_DIM;
    float acc = 0.f;
#pragma unroll 8
    for (int u = 0; u < U_DIM; u++)
        acc = fmaf(es[u], Hk[u * U_DIM + w], acc);
    out[((size_t)k * B_DIM + b) * U_DIM + w] = acc;
}

// ---------------------------------------------------------------------------
// 7) memory_bank[t,b] = X[b*T+t]   (float4)
// ---------------------------------------------------------------------------
__global__ void membank_k(const float* __restrict__ X, float* __restrict__ out)
{
    int grp = threadIdx.x >> 6;
    int n   = blockIdx.x * 4 + grp;
    int lu  = threadIdx.x & 63;
    int b = n / T_DIM, t = n % T_DIM;
    reinterpret_cast<float4*>(out)[((size_t)t * B_DIM + b) * U4 + lu] =
        reinterpret_cast<const float4*>(X)[(size_t)n * U4 + lu];
}

// ---------------------------------------------------------------------------
// Launch
// ---------------------------------------------------------------------------
extern "C" void kernel_launch(void* const* d_in, const int* in_sizes, int n_in,
                              void* d_out, int out_size)
{
    const int*   src       = (const int*)  d_in[0];
    const int*   arc_in    = (const int*)  d_in[1];
    const int*   arc_out   = (const int*)  d_in[2];
    const int*   lab_in    = (const int*)  d_in[3];
    const int*   lab_out   = (const int*)  d_in[4];
    const float* mask_in   = (const float*)d_in[5];
    const float* mask_out  = (const float*)d_in[6];
    const float* mask_loop = (const float*)d_in[7];
    const float* sent_mask = (const float*)d_in[8];
    const float* emb       = (const float*)d_in[9];
    const float* V_in      = (const float*)d_in[10];
    const float* b_in      = (const float*)d_in[11];
    const float* Vg_in     = (const float*)d_in[12];
    const float* bg_in     = (const float*)d_in[13];
    const float* V_out     = (const float*)d_in[14];
    const float* b_out     = (const float*)d_in[15];
    const float* Vg_out    = (const float*)d_in[16];
    const float* bg_out    = (const float*)d_in[17];
    const float* W_loop    = (const float*)d_in[18];
    const float* Wg_loop   = (const float*)d_in[19];
    const float* H         = (const float*)d_in[20];
    float* out = (float*)d_out;

    float *pX0, *pX1, *pXVin, *pXVout, *pXVloop, *pgin, *pgout, *pgloop, *penc;
    cudaGetSymbolAddress((void**)&pX0,     g_X0);
    cudaGetSymbolAddress((void**)&pX1,     g_X1);
    cudaGetSymbolAddress((void**)&pXVin,   g_XVin);
    cudaGetSymbolAddress((void**)&pXVout,  g_XVout);
    cudaGetSymbolAddress((void**)&pXVloop, g_XVloop);
    cudaGetSymbolAddress((void**)&pgin,    g_gin);
    cudaGetSymbolAddress((void**)&pgout,   g_gout);
    cudaGetSymbolAddress((void**)&pgloop,  g_gloop);
    cudaGetSymbolAddress((void**)&penc,    g_enc);

    embed_k<<<BT / 4, 256>>>(src, emb, pX0);

    float* Xcur = pX0;
    float* Xnxt = pX1;
    for (int l = 0; l < L_LAYERS; l++) {
        const size_t wOff  = (size_t)l * U_DIM * U_DIM;
        const size_t gOff  = (size_t)l * U_DIM;
        const size_t bOff  = (size_t)l * NL_LAB * U_DIM;
        const size_t bgOff = (size_t)l * NL_LAB;

        dim3 ggrid(BT / GBM, 6);
        gemm3_tf32_k<<<ggrid, 256>>>(Xcur,
                                     V_in + wOff, V_out + wOff, W_loop + wOff,
                                     pXVin, pXVout, pXVloop);
        gate_k<<<BT / 8, 256>>>(Xcur, Vg_in + gOff, Vg_out + gOff,
                                Wg_loop + gOff, pgin, pgout, pgloop);
        agg_k<<<BT / 4, 256>>>(pXVin, pXVout, pXVloop, pgin, pgout, pgloop,
                               arc_in, arc_out, lab_in, lab_out,
                               b_in + bOff, bg_in + bgOff,
                               b_out + bOff, bg_out + bgOff,
                               mask_in, mask_out, mask_loop, sent_mask, Xnxt);
        float* tmp = Xcur; Xcur = Xnxt; Xnxt = tmp;
    }

    enc_k<<<B_DIM, 64>>>(Xcur, sent_mask, penc);
    hall_k<<<dim3(B_DIM, 4), U_DIM>>>(penc, H, out);
    membank_k<<<BT / 4, 256>>>(Xcur, out + 4 * B_DIM * U_DIM);
}

// round 4
// speedup vs baseline: 2.5214x; 1.0392x over previous
#include <cuda_runtime.h>
#include <cuda_bf16.h>
#include <cstdint>

// Problem constants
#define L_LAYERS 2
#define U_DIM    256
#define U4       (U_DIM / 4)
#define NL_LAB   64
#define B_DIM    128
#define T_DIM    128
#define DEG      5
#define BT       (B_DIM * T_DIM)          // 16384 nodes
#define E_EDGES  (BT * DEG)               // 81920

// ---------------------------------------------------------------------------
// Scratch (device globals — no allocation allowed)
// ---------------------------------------------------------------------------
__device__ float g_X0[BT * U_DIM];
__device__ float g_X1[BT * U_DIM];
__device__ float g_XVin[BT * U_DIM];
__device__ float g_XVout[BT * U_DIM];
__device__ float g_XVloop[BT * U_DIM];
__device__ float g_gin[BT];
__device__ float g_gout[BT];
__device__ float g_gloop[BT];
__device__ float g_enc[B_DIM * U_DIM];

// ---------------------------------------------------------------------------
// helpers
// ---------------------------------------------------------------------------
__device__ __forceinline__ uint32_t f2tf32(float f) {
    uint32_t r;
    asm("cvt.rna.tf32.f32 %0, %1;" : "=r"(r) : "f"(f));
    return r;
}

__device__ __forceinline__ void mma_tf32(float* d, const uint32_t* a,
                                         const uint32_t* b) {
    asm volatile(
        "mma.sync.aligned.m16n8k8.row.col.f32.tf32.tf32.f32 "
        "{%0,%1,%2,%3}, {%4,%5,%6,%7}, {%8,%9}, {%0,%1,%2,%3};\n"
        : "+f"(d[0]), "+f"(d[1]), "+f"(d[2]), "+f"(d[3])
        : "r"(a[0]), "r"(a[1]), "r"(a[2]), "r"(a[3]), "r"(b[0]), "r"(b[1]));
}

__device__ __forceinline__ void cp16(void* dst, const void* src) {
    uint32_t d = (uint32_t)__cvta_generic_to_shared(dst);
    asm volatile("cp.async.cg.shared.global [%0], [%1], 16;\n"
                 :: "r"(d), "l"(src));
}
#define CP_COMMIT() asm volatile("cp.async.commit_group;\n" ::: "memory")
#define CP_WAIT1()  asm volatile("cp.async.wait_group 1;\n" ::: "memory")

// ---------------------------------------------------------------------------
// 1) Embedding gather (float4): X[n=b*T+t] = emb[src[t,b]]
// ---------------------------------------------------------------------------
__global__ void embed_k(const int* __restrict__ src,
                        const float* __restrict__ emb,
                        float* __restrict__ X)
{
    int grp = threadIdx.x >> 6;
    int n   = blockIdx.x * 4 + grp;
    int lu  = threadIdx.x & 63;
    int b = n / T_DIM, t = n % T_DIM;
    int tok = src[t * B_DIM + b];
    reinterpret_cast<float4*>(X)[(size_t)n * U4 + lu] =
        reinterpret_cast<const float4*>(emb)[(size_t)tok * U4 + lu];
}

// ---------------------------------------------------------------------------
// 2) Fused TF32 GEMM + gates.
//    grid(128, 7):
//      y in [0,6): C = A[16384,256] * W[256,256]; sel=y>>1 picks W/C,
//                  (y&1)*128 picks N half. 128x128 tile, BK=16, cp.async
//                  2-stage pipeline, 8 warps (4M x 2N), warp tile 32x64.
//      y == 6   : gate GEMVs (gin/gout/gloop), 128 nodes per block.
// ---------------------------------------------------------------------------
#define GBM 128
#define GBN 128
#define GBK 16
#define NTILES (U_DIM / GBK)

__global__ __launch_bounds__(256)
void gemm_gate_k(const float* __restrict__ A,
                 const float* __restrict__ W0, const float* __restrict__ W1,
                 const float* __restrict__ W2,
                 float* __restrict__ C0, float* __restrict__ C1,
                 float* __restrict__ C2,
                 const float* __restrict__ vgin,
                 const float* __restrict__ vgout,
                 const float* __restrict__ wgl,
                 float* __restrict__ gin, float* __restrict__ gout,
                 float* __restrict__ gloop)
{
    // ---------------- gate slice ----------------
    if (blockIdx.y == 6) {
        int warp = threadIdx.x >> 5;
        int lane = threadIdx.x & 31;
        const float4* v0 = reinterpret_cast<const float4*>(vgin);
        const float4* v1 = reinterpret_cast<const float4*>(vgout);
        const float4* v2 = reinterpret_cast<const float4*>(wgl);
#pragma unroll 1
        for (int i = 0; i < 16; i++) {
            int n = blockIdx.x * 128 + i * 8 + warp;
            const float4* xr =
                reinterpret_cast<const float4*>(A + (size_t)n * U_DIM);
            float s0 = 0.f, s1 = 0.f, s2 = 0.f;
#pragma unroll
            for (int k = lane; k < U4; k += 32) {
                float4 x = xr[k];
                float4 a = v0[k], b = v1[k], c = v2[k];
                s0 += x.x * a.x + x.y * a.y + x.z * a.z + x.w * a.w;
                s1 += x.x * b.x + x.y * b.y + x.z * b.z + x.w * b.w;
                s2 += x.x * c.x + x.y * c.y + x.z * c.z + x.w * c.w;
            }
#pragma unroll
            for (int off = 16; off > 0; off >>= 1) {
                s0 += __shfl_down_sync(0xffffffffu, s0, off);
                s1 += __shfl_down_sync(0xffffffffu, s1, off);
                s2 += __shfl_down_sync(0xffffffffu, s2, off);
            }
            if (lane == 0) { gin[n] = s0; gout[n] = s1; gloop[n] = s2; }
        }
        return;
    }

    // ---------------- GEMM slice ----------------
    const int sel     = blockIdx.y >> 1;
    const int colbase = (blockIdx.y & 1) * GBN;
    const float* __restrict__ W = (sel == 0) ? W0 : ((sel == 1) ? W1 : W2);
    float* __restrict__ C       = (sel == 0) ? C0 : ((sel == 1) ? C1 : C2);
    const int mbase = blockIdx.x * GBM;

    // fp32 tiles; converted to tf32 at fragment load.
    // As pitch 20 / Bs pitch 136 -> conflict-free fragment LDS.
    __shared__ __align__(16) float As[2][GBM][GBK + 4];
    __shared__ __align__(16) float Bs[2][GBK][GBN + 8];

    const int tid  = threadIdx.x;
    const int lane = tid & 31;
    const int warp = tid >> 5;
    const int wm   = (warp & 3) * 32;
    const int wn   = (warp >> 2) * 64;
    const int g    = lane >> 2;
    const int t    = lane & 3;

    // cp.async mappings: each thread copies 8 contiguous floats (2x 16B)
    const int aRow = tid >> 1;            // 0..127
    const int aK4  = (tid & 1) * 8;       // 0 or 8
    const int bK   = tid >> 4;            // 0..15
    const int bN4  = (tid & 15) * 8;      // 0..120

    const float* Abase = A + (size_t)(mbase + aRow) * U_DIM + aK4;
    const float* Wbase = W + (size_t)bK * U_DIM + colbase + bN4;

    float acc[2][8][4];
#pragma unroll
    for (int mi = 0; mi < 2; mi++)
#pragma unroll
        for (int ni = 0; ni < 8; ni++)
#pragma unroll
            for (int c = 0; c < 4; c++) acc[mi][ni][c] = 0.f;

    // prologue: tile 0 into stage 0
    cp16(&As[0][aRow][aK4],     Abase);
    cp16(&As[0][aRow][aK4 + 4], Abase + 4);
    cp16(&Bs[0][bK][bN4],       Wbase);
    cp16(&Bs[0][bK][bN4 + 4],   Wbase + 4);     // FIXED: was +64
    CP_COMMIT();

    for (int tile = 0; tile < NTILES; tile++) {
        int nxt = tile + 1;
        if (nxt < NTILES) {
            int s = nxt & 1;
            int k0 = nxt * GBK;
            cp16(&As[s][aRow][aK4],     Abase + k0);
            cp16(&As[s][aRow][aK4 + 4], Abase + k0 + 4);
            cp16(&Bs[s][bK][bN4],       Wbase + (size_t)k0 * U_DIM);
            cp16(&Bs[s][bK][bN4 + 4],   Wbase + (size_t)k0 * U_DIM + 4); // FIXED
        }
        CP_COMMIT();
        CP_WAIT1();
        __syncthreads();

        const int st = tile & 1;
#pragma unroll
        for (int ks = 0; ks < GBK; ks += 8) {
            uint32_t afr[2][4];
#pragma unroll
            for (int mi = 0; mi < 2; mi++) {
                int m0 = wm + mi * 16;
                afr[mi][0] = f2tf32(As[st][m0 + g][ks + t]);
                afr[mi][1] = f2tf32(As[st][m0 + g + 8][ks + t]);
                afr[mi][2] = f2tf32(As[st][m0 + g][ks + t + 4]);
                afr[mi][3] = f2tf32(As[st][m0 + g + 8][ks + t + 4]);
            }
            uint32_t bfr[8][2];
#pragma unroll
            for (int ni = 0; ni < 8; ni++) {
                int n0 = wn + ni * 8 + g;
                bfr[ni][0] = f2tf32(Bs[st][ks + t][n0]);
                bfr[ni][1] = f2tf32(Bs[st][ks + t + 4][n0]);
            }
#pragma unroll
            for (int mi = 0; mi < 2; mi++)
#pragma unroll
                for (int ni = 0; ni < 8; ni++)
                    mma_tf32(acc[mi][ni], afr[mi], bfr[ni]);
        }
        __syncthreads();   // stage reuse fence
    }

    // epilogue
#pragma unroll
    for (int mi = 0; mi < 2; mi++) {
#pragma unroll
        for (int ni = 0; ni < 8; ni++) {
            int row = mbase + wm + mi * 16 + g;
            int col = colbase + wn + ni * 8 + 2 * t;
            float2 v0 = make_float2(acc[mi][ni][0], acc[mi][ni][1]);
            float2 v1 = make_float2(acc[mi][ni][2], acc[mi][ni][3]);
            *reinterpret_cast<float2*>(&C[(size_t)row * U_DIM + col])       = v0;
            *reinterpret_cast<float2*>(&C[(size_t)(row + 8) * U_DIM + col]) = v1;
        }
    }
}

// ---------------------------------------------------------------------------
// 3) Edge aggregation, float4: 64 threads/node, 4 nodes/block.
//    tb_layout=1 -> write [t,b,u] (membank/d_out) instead of node-major.
// ---------------------------------------------------------------------------
__global__ __launch_bounds__(256)
void agg_k(const float* __restrict__ XVin,
           const float* __restrict__ XVout,
           const float* __restrict__ XVloop,
           const float* __restrict__ gin,
           const float* __restrict__ gout,
           const float* __restrict__ gloop,
           const int* __restrict__ arc_in,
           const int* __restrict__ arc_out,
           const int* __restrict__ lab_in,
           const int* __restrict__ lab_out,
           const float* __restrict__ b_in,
           const float* __restrict__ bg_in,
           const float* __restrict__ b_out,
           const float* __restrict__ bg_out,
           const float* __restrict__ mask_in,
           const float* __restrict__ mask_out,
           const float* __restrict__ mask_loop,
           const float* __restrict__ sent_mask,
           float* __restrict__ Y, int tb_layout)
{
    int grp = threadIdx.x >> 6;
    int n   = blockIdx.x * 4 + grp;
    int lu  = threadIdx.x & 63;

    __shared__ float p_in[4][DEG], p_out[4][DEG], p_loop[4];
    __shared__ int   s_in[4][DEG], s_out[4][DEG], l_in[4][DEG], l_out[4][DEG];

    if (lu < DEG) {
        int d = lu, e = n * DEG + d;
        int si = arc_in[e] * T_DIM + arc_in[E_EDGES + e];
        int li = lab_in[e];
        float gi = gin[si] + bg_in[li];
        p_in[grp][d] = (1.f / (1.f + __expf(-gi))) * mask_in[n * DEG + d];
        s_in[grp][d] = si; l_in[grp][d] = li;
    } else if (lu < 2 * DEG) {
        int d = lu - DEG, e = n * DEG + d;
        int so = arc_out[e] * T_DIM + arc_out[E_EDGES + e];
        int lo = lab_out[e];
        float go = gout[so] + bg_out[lo];
        p_out[grp][d] = (1.f / (1.f + __expf(-go))) * mask_out[n * DEG + d];
        s_out[grp][d] = so; l_out[grp][d] = lo;
    } else if (lu == 2 * DEG) {
        p_loop[grp] = (1.f / (1.f + __expf(-gloop[n]))) * mask_loop[n];
    }
    __syncthreads();

    const float4* XVin4   = reinterpret_cast<const float4*>(XVin);
    const float4* XVout4  = reinterpret_cast<const float4*>(XVout);
    const float4* XVloop4 = reinterpret_cast<const float4*>(XVloop);
    const float4* bin4    = reinterpret_cast<const float4*>(b_in);
    const float4* bout4   = reinterpret_cast<const float4*>(b_out);

    float pl = p_loop[grp];
    float4 h = XVloop4[(size_t)n * U4 + lu];
    float4 acc = make_float4(pl * h.x, pl * h.y, pl * h.z, pl * h.w);

#pragma unroll
    for (int d = 0; d < DEG; d++) {
        float p = p_in[grp][d];
        float4 v = XVin4[(size_t)s_in[grp][d] * U4 + lu];
        float4 bb = bin4[(size_t)l_in[grp][d] * U4 + lu];
        acc.x = fmaf(p, v.x + bb.x, acc.x);
        acc.y = fmaf(p, v.y + bb.y, acc.y);
        acc.z = fmaf(p, v.z + bb.z, acc.z);
        acc.w = fmaf(p, v.w + bb.w, acc.w);
        p = p_out[grp][d];
        v = XVout4[(size_t)s_out[grp][d] * U4 + lu];
        bb = bout4[(size_t)l_out[grp][d] * U4 + lu];
        acc.x = fmaf(p, v.x + bb.x, acc.x);
        acc.y = fmaf(p, v.y + bb.y, acc.y);
        acc.z = fmaf(p, v.z + bb.z, acc.z);
        acc.w = fmaf(p, v.w + bb.w, acc.w);
    }
    int b = n / T_DIM, t = n % T_DIM;
    float sm = sent_mask[t * B_DIM + b];
    acc.x = fmaxf(acc.x, 0.f) * sm;
    acc.y = fmaxf(acc.y, 0.f) * sm;
    acc.z = fmaxf(acc.z, 0.f) * sm;
    acc.w = fmaxf(acc.w, 0.f) * sm;
    size_t oidx = tb_layout ? ((size_t)t * B_DIM + b) * U4 + lu
                            : (size_t)n * U4 + lu;
    reinterpret_cast<float4*>(Y)[oidx] = acc;
}

// ---------------------------------------------------------------------------
// 4) enc[b] from membank layout: enc[b,u] = (sum_t MB[t,b,u]) / mask_sum[b]
// ---------------------------------------------------------------------------
__global__ void enc_k(const float* __restrict__ MB,
                      const float* __restrict__ sent_mask,
                      float* __restrict__ enc)
{
    int b = blockIdx.x;
    int u = threadIdx.x;  // 0..63
    const float4* M4 = reinterpret_cast<const float4*>(MB);
    float4 s = make_float4(0.f, 0.f, 0.f, 0.f);
#pragma unroll 4
    for (int t = 0; t < T_DIM; t++) {
        float4 v = M4[((size_t)t * B_DIM + b) * U4 + u];
        s.x += v.x; s.y += v.y; s.z += v.z; s.w += v.w;
    }
    __shared__ float ms;
    if (u == 0) {
        float m = 0.f;
        for (int t = 0; t < T_DIM; t++) m += sent_mask[t * B_DIM + b];
        ms = m;
    }
    __syncthreads();
    float inv = 1.f / ms;
    s.x *= inv; s.y *= inv; s.z *= inv; s.w *= inv;
    reinterpret_cast<float4*>(enc)[b * U4 + u] = s;
}

// ---------------------------------------------------------------------------
// 5) h_all[k,b,w] = sum_u enc[b,u] * H[k,u,w]
// ---------------------------------------------------------------------------
__global__ void hall_k(const float* __restrict__ enc,
                       const float* __restrict__ H,
                       float* __restrict__ out)
{
    int k = blockIdx.y, b = blockIdx.x, w = threadIdx.x;
    __shared__ float es[U_DIM];
    es[w] = enc[b * U_DIM + w];
    __syncthreads();
    const float* Hk = H + (size_t)k * U_DIM * U_DIM;
    float acc = 0.f;
#pragma unroll 8
    for (int u = 0; u < U_DIM; u++)
        acc = fmaf(es[u], Hk[u * U_DIM + w], acc);
    out[((size_t)k * B_DIM + b) * U_DIM + w] = acc;
}

// ---------------------------------------------------------------------------
// Launch
// ---------------------------------------------------------------------------
extern "C" void kernel_launch(void* const* d_in, const int* in_sizes, int n_in,
                              void* d_out, int out_size)
{
    const int*   src       = (const int*)  d_in[0];
    const int*   arc_in    = (const int*)  d_in[1];
    const int*   arc_out   = (const int*)  d_in[2];
    const int*   lab_in    = (const int*)  d_in[3];
    const int*   lab_out   = (const int*)  d_in[4];
    const float* mask_in   = (const float*)d_in[5];
    const float* mask_out  = (const float*)d_in[6];
    const float* mask_loop = (const float*)d_in[7];
    const float* sent_mask = (const float*)d_in[8];
    const float* emb       = (const float*)d_in[9];
    const float* V_in      = (const float*)d_in[10];
    const float* b_in      = (const float*)d_in[11];
    const float* Vg_in     = (const float*)d_in[12];
    const float* bg_in     = (const float*)d_in[13];
    const float* V_out     = (const float*)d_in[14];
    const float* b_out     = (const float*)d_in[15];
    const float* Vg_out    = (const float*)d_in[16];
    const float* bg_out    = (const float*)d_in[17];
    const float* W_loop    = (const float*)d_in[18];
    const float* Wg_loop   = (const float*)d_in[19];
    const float* H         = (const float*)d_in[20];
    float* out = (float*)d_out;

    float *pX0, *pX1, *pXVin, *pXVout, *pXVloop, *pgin, *pgout, *pgloop, *penc;
    cudaGetSymbolAddress((void**)&pX0,     g_X0);
    cudaGetSymbolAddress((void**)&pX1,     g_X1);
    cudaGetSymbolAddress((void**)&pXVin,   g_XVin);
    cudaGetSymbolAddress((void**)&pXVout,  g_XVout);
    cudaGetSymbolAddress((void**)&pXVloop, g_XVloop);
    cudaGetSymbolAddress((void**)&pgin,    g_gin);
    cudaGetSymbolAddress((void**)&pgout,   g_gout);
    cudaGetSymbolAddress((void**)&pgloop,  g_gloop);
    cudaGetSymbolAddress((void**)&penc,    g_enc);

    float* memOut = out + 4 * B_DIM * U_DIM;   // membank region of d_out

    embed_k<<<BT / 4, 256>>>(src, emb, pX0);

    float* Xcur = pX0;
    for (int l = 0; l < L_LAYERS; l++) {
        const size_t wOff  = (size_t)l * U_DIM * U_DIM;
        const size_t gOff  = (size_t)l * U_DIM;
        const size_t bOff  = (size_t)l * NL_LAB * U_DIM;
        const size_t bgOff = (size_t)l * NL_LAB;
        const int last = (l == L_LAYERS - 1);

        dim3 ggrid(BT / GBM, 7);
        gemm_gate_k<<<ggrid, 256>>>(Xcur,
                                    V_in + wOff, V_out + wOff, W_loop + wOff,
                                    pXVin, pXVout, pXVloop,
                                    Vg_in + gOff, Vg_out + gOff, Wg_loop + gOff,
                                    pgin, pgout, pgloop);
        agg_k<<<BT / 4, 256>>>(pXVin, pXVout, pXVloop, pgin, pgout, pgloop,
                               arc_in, arc_out, lab_in, lab_out,
                               b_in + bOff, bg_in + bgOff,
                               b_out + bOff, bg_out + bgOff,
                               mask_in, mask_out, mask_loop, sent_mask,
                               last ? memOut : pX1, last ? 1 : 0);
        Xcur = pX1;
    }

    enc_k<<<B_DIM, 64>>>(memOut, sent_mask, penc);
    hall_k<<<dim3(B_DIM, 4), U_DIM>>>(penc, H, out);
}

// round 5
// speedup vs baseline: 2.5275x; 1.0024x over previous
#include <cuda_runtime.h>
#include <cuda_bf16.h>
#include <cstdint>

// Problem constants
#define L_LAYERS 2
#define U_DIM    256
#define U4       (U_DIM / 4)
#define NL_LAB   64
#define B_DIM    128
#define T_DIM    128
#define DEG      5
#define BT       (B_DIM * T_DIM)          // 16384 nodes
#define E_EDGES  (BT * DEG)               // 81920
#define WSZ      (U_DIM * U_DIM)          // 65536 floats per weight matrix

// ---------------------------------------------------------------------------
// Scratch (device globals — no allocation allowed)
// ---------------------------------------------------------------------------
__device__ float g_X0[BT * U_DIM];
__device__ float g_X1[BT * U_DIM];
__device__ float g_Xtf[BT * U_DIM];               // tf32-rounded copy of X
__device__ float g_Wtf[L_LAYERS * 3 * WSZ];       // tf32-rounded weights
__device__ float g_XVin[BT * U_DIM];
__device__ float g_XVout[BT * U_DIM];
__device__ float g_XVloop[BT * U_DIM];
__device__ float g_gin[BT];
__device__ float g_gout[BT];
__device__ float g_gloop[BT];
__device__ float g_enc[B_DIM * U_DIM];

// ---------------------------------------------------------------------------
// helpers
// ---------------------------------------------------------------------------
__device__ __forceinline__ uint32_t f2tf32(float f) {
    uint32_t r;
    asm("cvt.rna.tf32.f32 %0, %1;" : "=r"(r) : "f"(f));
    return r;
}

__device__ __forceinline__ float4 cvt4(float4 v) {
    float4 o;
    o.x = __uint_as_float(f2tf32(v.x));
    o.y = __uint_as_float(f2tf32(v.y));
    o.z = __uint_as_float(f2tf32(v.z));
    o.w = __uint_as_float(f2tf32(v.w));
    return o;
}

__device__ __forceinline__ void mma_tf32(float* d, const uint32_t* a,
                                         const uint32_t* b) {
    asm volatile(
        "mma.sync.aligned.m16n8k8.row.col.f32.tf32.tf32.f32 "
        "{%0,%1,%2,%3}, {%4,%5,%6,%7}, {%8,%9}, {%0,%1,%2,%3};\n"
        : "+f"(d[0]), "+f"(d[1]), "+f"(d[2]), "+f"(d[3])
        : "r"(a[0]), "r"(a[1]), "r"(a[2]), "r"(a[3]), "r"(b[0]), "r"(b[1]));
}

__device__ __forceinline__ void cp16(void* dst, const void* src) {
    uint32_t d = (uint32_t)__cvta_generic_to_shared(dst);
    asm volatile("cp.async.cg.shared.global [%0], [%1], 16;\n"
                 :: "r"(d), "l"(src));
}
#define CP_COMMIT() asm volatile("cp.async.commit_group;\n" ::: "memory")
#define CP_WAIT1()  asm volatile("cp.async.wait_group 1;\n" ::: "memory")

// ---------------------------------------------------------------------------
// 0) Weight conversion: all L*3 weight matrices -> tf32 bits, once.
//    grid: L*3*WSZ/4/256 = 384 blocks.
// ---------------------------------------------------------------------------
__global__ void cvtw_k(const float* __restrict__ Vin,
                       const float* __restrict__ Vout,
                       const float* __restrict__ Wloop,
                       float* __restrict__ out)
{
    int idx = blockIdx.x * 256 + threadIdx.x;     // float4 index
    int l   = idx / (3 * WSZ / 4);
    int r   = idx % (3 * WSZ / 4);
    int sel = r / (WSZ / 4);
    int e4  = r % (WSZ / 4);
    const float* src = (sel == 0) ? Vin : ((sel == 1) ? Vout : Wloop);
    float4 v = reinterpret_cast<const float4*>(src + (size_t)l * WSZ)[e4];
    reinterpret_cast<float4*>(out)[idx] = cvt4(v);
}

// ---------------------------------------------------------------------------
// 1) Embedding gather: X[n=b*T+t] = emb[src[t,b]]; also tf32 copy.
// ---------------------------------------------------------------------------
__global__ void embed_k(const int* __restrict__ src,
                        const float* __restrict__ emb,
                        float* __restrict__ X,
                        float* __restrict__ Xtf)
{
    int grp = threadIdx.x >> 6;
    int n   = blockIdx.x * 4 + grp;
    int lu  = threadIdx.x & 63;
    int b = n / T_DIM, t = n % T_DIM;
    int tok = src[t * B_DIM + b];
    float4 v = reinterpret_cast<const float4*>(emb)[(size_t)tok * U4 + lu];
    reinterpret_cast<float4*>(X)[(size_t)n * U4 + lu]   = v;
    reinterpret_cast<float4*>(Xtf)[(size_t)n * U4 + lu] = cvt4(v);
}

// ---------------------------------------------------------------------------
// 2) Fused TF32 GEMM + gates.
//    grid(128, 7):
//      y in [0,6): C = Atf[16384,256] * Wtf[sel]; (y&1)*128 picks N half.
//                  128x128 tile, BK=16, cp.async 2-stage, 8 warps (4Mx2N).
//                  NO cvt in mainloop — operands pre-rounded to tf32.
//      y == 6   : gate GEMVs on ORIGINAL A (full fp32 precision).
// ---------------------------------------------------------------------------
#define GBM 128
#define GBN 128
#define GBK 16
#define NTILES (U_DIM / GBK)

__global__ __launch_bounds__(256)
void gemm_gate_k(const float* __restrict__ Atf,
                 const float* __restrict__ Wtf,   // [3][WSZ] for this layer
                 float* __restrict__ C0, float* __restrict__ C1,
                 float* __restrict__ C2,
                 const float* __restrict__ Aorig,
                 const float* __restrict__ vgin,
                 const float* __restrict__ vgout,
                 const float* __restrict__ wgl,
                 float* __restrict__ gin, float* __restrict__ gout,
                 float* __restrict__ gloop)
{
    // ---------------- gate slice ----------------
    if (blockIdx.y == 6) {
        int warp = threadIdx.x >> 5;
        int lane = threadIdx.x & 31;
        const float4* v0 = reinterpret_cast<const float4*>(vgin);
        const float4* v1 = reinterpret_cast<const float4*>(vgout);
        const float4* v2 = reinterpret_cast<const float4*>(wgl);
#pragma unroll 1
        for (int i = 0; i < 16; i++) {
            int n = blockIdx.x * 128 + i * 8 + warp;
            const float4* xr =
                reinterpret_cast<const float4*>(Aorig + (size_t)n * U_DIM);
            float s0 = 0.f, s1 = 0.f, s2 = 0.f;
#pragma unroll
            for (int k = lane; k < U4; k += 32) {
                float4 x = xr[k];
                float4 a = v0[k], b = v1[k], c = v2[k];
                s0 += x.x * a.x + x.y * a.y + x.z * a.z + x.w * a.w;
                s1 += x.x * b.x + x.y * b.y + x.z * b.z + x.w * b.w;
                s2 += x.x * c.x + x.y * c.y + x.z * c.z + x.w * c.w;
            }
#pragma unroll
            for (int off = 16; off > 0; off >>= 1) {
                s0 += __shfl_down_sync(0xffffffffu, s0, off);
                s1 += __shfl_down_sync(0xffffffffu, s1, off);
                s2 += __shfl_down_sync(0xffffffffu, s2, off);
            }
            if (lane == 0) { gin[n] = s0; gout[n] = s1; gloop[n] = s2; }
        }
        return;
    }

    // ---------------- GEMM slice ----------------
    const int sel     = blockIdx.y >> 1;
    const int colbase = (blockIdx.y & 1) * GBN;
    const float* __restrict__ W = Wtf + (size_t)sel * WSZ;
    float* __restrict__ C       = (sel == 0) ? C0 : ((sel == 1) ? C1 : C2);
    const int mbase = blockIdx.x * GBM;

    // As pitch 20 / Bs pitch 136 -> conflict-free fragment LDS.
    __shared__ __align__(16) float As[2][GBM][GBK + 4];
    __shared__ __align__(16) float Bs[2][GBK][GBN + 8];

    const int tid  = threadIdx.x;
    const int lane = tid & 31;
    const int warp = tid >> 5;
    const int wm   = (warp & 3) * 32;
    const int wn   = (warp >> 2) * 64;
    const int g    = lane >> 2;
    const int t    = lane & 3;

    const int aRow = tid >> 1;            // 0..127
    const int aK4  = (tid & 1) * 8;       // 0 or 8
    const int bK   = tid >> 4;            // 0..15
    const int bN4  = (tid & 15) * 8;      // 0..120

    const float* Abase = Atf + (size_t)(mbase + aRow) * U_DIM + aK4;
    const float* Wbase = W + (size_t)bK * U_DIM + colbase + bN4;

    float acc[2][8][4];
#pragma unroll
    for (int mi = 0; mi < 2; mi++)
#pragma unroll
        for (int ni = 0; ni < 8; ni++)
#pragma unroll
            for (int c = 0; c < 4; c++) acc[mi][ni][c] = 0.f;

    // prologue: tile 0 into stage 0
    cp16(&As[0][aRow][aK4],     Abase);
    cp16(&As[0][aRow][aK4 + 4], Abase + 4);
    cp16(&Bs[0][bK][bN4],       Wbase);
    cp16(&Bs[0][bK][bN4 + 4],   Wbase + 4);
    CP_COMMIT();

    for (int tile = 0; tile < NTILES; tile++) {
        int nxt = tile + 1;
        if (nxt < NTILES) {
            int s = nxt & 1;
            int k0 = nxt * GBK;
            cp16(&As[s][aRow][aK4],     Abase + k0);
            cp16(&As[s][aRow][aK4 + 4], Abase + k0 + 4);
            cp16(&Bs[s][bK][bN4],       Wbase + (size_t)k0 * U_DIM);
            cp16(&Bs[s][bK][bN4 + 4],   Wbase + (size_t)k0 * U_DIM + 4);
        }
        CP_COMMIT();
        CP_WAIT1();
        __syncthreads();

        const int st = tile & 1;
#pragma unroll
        for (int ks = 0; ks < GBK; ks += 8) {
            uint32_t afr[2][4];
#pragma unroll
            for (int mi = 0; mi < 2; mi++) {
                int m0 = wm + mi * 16;
                afr[mi][0] = __float_as_uint(As[st][m0 + g][ks + t]);
                afr[mi][1] = __float_as_uint(As[st][m0 + g + 8][ks + t]);
                afr[mi][2] = __float_as_uint(As[st][m0 + g][ks + t + 4]);
                afr[mi][3] = __float_as_uint(As[st][m0 + g + 8][ks + t + 4]);
            }
            uint32_t bfr[8][2];
#pragma unroll
            for (int ni = 0; ni < 8; ni++) {
                int n0 = wn + ni * 8 + g;
                bfr[ni][0] = __float_as_uint(Bs[st][ks + t][n0]);
                bfr[ni][1] = __float_as_uint(Bs[st][ks + t + 4][n0]);
            }
#pragma unroll
            for (int mi = 0; mi < 2; mi++)
#pragma unroll
                for (int ni = 0; ni < 8; ni++)
                    mma_tf32(acc[mi][ni], afr[mi], bfr[ni]);
        }
        __syncthreads();
    }

    // epilogue
#pragma unroll
    for (int mi = 0; mi < 2; mi++) {
#pragma unroll
        for (int ni = 0; ni < 8; ni++) {
            int row = mbase + wm + mi * 16 + g;
            int col = colbase + wn + ni * 8 + 2 * t;
            float2 v0 = make_float2(acc[mi][ni][0], acc[mi][ni][1]);
            float2 v1 = make_float2(acc[mi][ni][2], acc[mi][ni][3]);
            *reinterpret_cast<float2*>(&C[(size_t)row * U_DIM + col])       = v0;
            *reinterpret_cast<float2*>(&C[(size_t)(row + 8) * U_DIM + col]) = v1;
        }
    }
}

// ---------------------------------------------------------------------------
// 3) Edge aggregation, float4: 64 threads/node, 4 nodes/block.
//    tb_layout=1 -> write [t,b,u] (membank/d_out).
//    Ytf != nullptr -> also write tf32-rounded copy (next layer's GEMM A).
// ---------------------------------------------------------------------------
__global__ __launch_bounds__(256)
void agg_k(const float* __restrict__ XVin,
           const float* __restrict__ XVout,
           const float* __restrict__ XVloop,
           const float* __restrict__ gin,
           const float* __restrict__ gout,
           const float* __restrict__ gloop,
           const int* __restrict__ arc_in,
           const int* __restrict__ arc_out,
           const int* __restrict__ lab_in,
           const int* __restrict__ lab_out,
           const float* __restrict__ b_in,
           const float* __restrict__ bg_in,
           const float* __restrict__ b_out,
           const float* __restrict__ bg_out,
           const float* __restrict__ mask_in,
           const float* __restrict__ mask_out,
           const float* __restrict__ mask_loop,
           const float* __restrict__ sent_mask,
           float* __restrict__ Y, float* __restrict__ Ytf, int tb_layout)
{
    int grp = threadIdx.x >> 6;
    int n   = blockIdx.x * 4 + grp;
    int lu  = threadIdx.x & 63;

    __shared__ float p_in[4][DEG], p_out[4][DEG], p_loop[4];
    __shared__ int   s_in[4][DEG], s_out[4][DEG], l_in[4][DEG], l_out[4][DEG];

    if (lu < DEG) {
        int d = lu, e = n * DEG + d;
        int si = arc_in[e] * T_DIM + arc_in[E_EDGES + e];
        int li = lab_in[e];
        float gi = gin[si] + bg_in[li];
        p_in[grp][d] = (1.f / (1.f + __expf(-gi))) * mask_in[n * DEG + d];
        s_in[grp][d] = si; l_in[grp][d] = li;
    } else if (lu < 2 * DEG) {
        int d = lu - DEG, e = n * DEG + d;
        int so = arc_out[e] * T_DIM + arc_out[E_EDGES + e];
        int lo = lab_out[e];
        float go = gout[so] + bg_out[lo];
        p_out[grp][d] = (1.f / (1.f + __expf(-go))) * mask_out[n * DEG + d];
        s_out[grp][d] = so; l_out[grp][d] = lo;
    } else if (lu == 2 * DEG) {
        p_loop[grp] = (1.f / (1.f + __expf(-gloop[n]))) * mask_loop[n];
    }
    __syncthreads();

    const float4* XVin4   = reinterpret_cast<const float4*>(XVin);
    const float4* XVout4  = reinterpret_cast<const float4*>(XVout);
    const float4* XVloop4 = reinterpret_cast<const float4*>(XVloop);
    const float4* bin4    = reinterpret_cast<const float4*>(b_in);
    const float4* bout4   = reinterpret_cast<const float4*>(b_out);

    float pl = p_loop[grp];
    float4 h = XVloop4[(size_t)n * U4 + lu];
    float4 acc = make_float4(pl * h.x, pl * h.y, pl * h.z, pl * h.w);

#pragma unroll
    for (int d = 0; d < DEG; d++) {
        float p = p_in[grp][d];
        float4 v = XVin4[(size_t)s_in[grp][d] * U4 + lu];
        float4 bb = bin4[(size_t)l_in[grp][d] * U4 + lu];
        acc.x = fmaf(p, v.x + bb.x, acc.x);
        acc.y = fmaf(p, v.y + bb.y, acc.y);
        acc.z = fmaf(p, v.z + bb.z, acc.z);
        acc.w = fmaf(p, v.w + bb.w, acc.w);
        p = p_out[grp][d];
        v = XVout4[(size_t)s_out[grp][d] * U4 + lu];
        bb = bout4[(size_t)l_out[grp][d] * U4 + lu];
        acc.x = fmaf(p, v.x + bb.x, acc.x);
        acc.y = fmaf(p, v.y + bb.y, acc.y);
        acc.z = fmaf(p, v.z + bb.z, acc.z);
        acc.w = fmaf(p, v.w + bb.w, acc.w);
    }
    int b = n / T_DIM, t = n % T_DIM;
    float sm = sent_mask[t * B_DIM + b];
    acc.x = fmaxf(acc.x, 0.f) * sm;
    acc.y = fmaxf(acc.y, 0.f) * sm;
    acc.z = fmaxf(acc.z, 0.f) * sm;
    acc.w = fmaxf(acc.w, 0.f) * sm;
    size_t oidx = tb_layout ? ((size_t)t * B_DIM + b) * U4 + lu
                            : (size_t)n * U4 + lu;
    reinterpret_cast<float4*>(Y)[oidx] = acc;
    if (Ytf)
        reinterpret_cast<float4*>(Ytf)[(size_t)n * U4 + lu] = cvt4(acc);
}

// ---------------------------------------------------------------------------
// 4) enc[b] from membank layout
// ---------------------------------------------------------------------------
__global__ void enc_k(const float* __restrict__ MB,
                      const float* __restrict__ sent_mask,
                      float* __restrict__ enc)
{
    int b = blockIdx.x;
    int u = threadIdx.x;  // 0..63
    const float4* M4 = reinterpret_cast<const float4*>(MB);
    float4 s = make_float4(0.f, 0.f, 0.f, 0.f);
#pragma unroll 4
    for (int t = 0; t < T_DIM; t++) {
        float4 v = M4[((size_t)t * B_DIM + b) * U4 + u];
        s.x += v.x; s.y += v.y; s.z += v.z; s.w += v.w;
    }
    __shared__ float ms;
    if (u == 0) {
        float m = 0.f;
        for (int t = 0; t < T_DIM; t++) m += sent_mask[t * B_DIM + b];
        ms = m;
    }
    __syncthreads();
    float inv = 1.f / ms;
    s.x *= inv; s.y *= inv; s.z *= inv; s.w *= inv;
    reinterpret_cast<float4*>(enc)[b * U4 + u] = s;
}

// ---------------------------------------------------------------------------
// 5) h_all[k,b,w] = sum_u enc[b,u] * H[k,u,w]
// ---------------------------------------------------------------------------
__global__ void hall_k(const float* __restrict__ enc,
                       const float* __restrict__ H,
                       float* __restrict__ out)
{
    int k = blockIdx.y, b = blockIdx.x, w = threadIdx.x;
    __shared__ float es[U_DIM];
    es[w] = enc[b * U_DIM + w];
    __syncthreads();
    const float* Hk = H + (size_t)k * U_DIM * U_DIM;
    float acc = 0.f;
#pragma unroll 8
    for (int u = 0; u < U_DIM; u++)
        acc = fmaf(es[u], Hk[u * U_DIM + w], acc);
    out[((size_t)k * B_DIM + b) * U_DIM + w] = acc;
}

// ---------------------------------------------------------------------------
// Launch
// ---------------------------------------------------------------------------
extern "C" void kernel_launch(void* const* d_in, const int* in_sizes, int n_in,
                              void* d_out, int out_size)
{
    const int*   src       = (const int*)  d_in[0];
    const int*   arc_in    = (const int*)  d_in[1];
    const int*   arc_out   = (const int*)  d_in[2];
    const int*   lab_in    = (const int*)  d_in[3];
    const int*   lab_out   = (const int*)  d_in[4];
    const float* mask_in   = (const float*)d_in[5];
    const float* mask_out  = (const float*)d_in[6];
    const float* mask_loop = (const float*)d_in[7];
    const float* sent_mask = (const float*)d_in[8];
    const float* emb       = (const float*)d_in[9];
    const float* V_in      = (const float*)d_in[10];
    const float* b_in      = (const float*)d_in[11];
    const float* Vg_in     = (const float*)d_in[12];
    const float* bg_in     = (const float*)d_in[13];
    const float* V_out     = (const float*)d_in[14];
    const float* b_out     = (const float*)d_in[15];
    const float* Vg_out    = (const float*)d_in[16];
    const float* bg_out    = (const float*)d_in[17];
    const float* W_loop    = (const float*)d_in[18];
    const float* Wg_loop   = (const float*)d_in[19];
    const float* H         = (const float*)d_in[20];
    float* out = (float*)d_out;

    float *pX0, *pX1, *pXtf, *pWtf, *pXVin, *pXVout, *pXVloop;
    float *pgin, *pgout, *pgloop, *penc;
    cudaGetSymbolAddress((void**)&pX0,     g_X0);
    cudaGetSymbolAddress((void**)&pX1,     g_X1);
    cudaGetSymbolAddress((void**)&pXtf,    g_Xtf);
    cudaGetSymbolAddress((void**)&pWtf,    g_Wtf);
    cudaGetSymbolAddress((void**)&pXVin,   g_XVin);
    cudaGetSymbolAddress((void**)&pXVout,  g_XVout);
    cudaGetSymbolAddress((void**)&pXVloop, g_XVloop);
    cudaGetSymbolAddress((void**)&pgin,    g_gin);
    cudaGetSymbolAddress((void**)&pgout,   g_gout);
    cudaGetSymbolAddress((void**)&pgloop,  g_gloop);
    cudaGetSymbolAddress((void**)&penc,    g_enc);

    float* memOut = out + 4 * B_DIM * U_DIM;   // membank region of d_out

    // convert all weights (both layers) + embed (with tf32 copy)
    cvtw_k<<<L_LAYERS * 3 * WSZ / 4 / 256, 256>>>(V_in, V_out, W_loop, pWtf);
    embed_k<<<BT / 4, 256>>>(src, emb, pX0, pXtf);

    float* Xcur = pX0;
    for (int l = 0; l < L_LAYERS; l++) {
        const size_t gOff  = (size_t)l * U_DIM;
        const size_t bOff  = (size_t)l * NL_LAB * U_DIM;
        const size_t bgOff = (size_t)l * NL_LAB;
        const int last = (l == L_LAYERS - 1);

        dim3 ggrid(BT / GBM, 7);
        gemm_gate_k<<<ggrid, 256>>>(pXtf, pWtf + (size_t)l * 3 * WSZ,
                                    pXVin, pXVout, pXVloop,
                                    Xcur,
                                    Vg_in + gOff, Vg_out + gOff, Wg_loop + gOff,
                                    pgin, pgout, pgloop);
        agg_k<<<BT / 4, 256>>>(pXVin, pXVout, pXVloop, pgin, pgout, pgloop,
                               arc_in, arc_out, lab_in, lab_out,
                               b_in + bOff, bg_in + bgOff,
                               b_out + bOff, bg_out + bgOff,
                               mask_in, mask_out, mask_loop, sent_mask,
                               last ? memOut : pX1,
                               last ? nullptr : pXtf,
                               last ? 1 : 0);
        Xcur = pX1;
    }

    enc_k<<<B_DIM, 64>>>(memOut, sent_mask, penc);
    hall_k<<<dim3(B_DIM, 4), U_DIM>>>(penc, H, out);
}

// round 7
// speedup vs baseline: 2.6971x; 1.0671x over previous
#include <cuda_runtime.h>
#include <cuda_bf16.h>
#include <cstdint>

// Problem constants
#define L_LAYERS 2
#define U_DIM    256
#define U4       (U_DIM / 4)
#define NL_LAB   64
#define B_DIM    128
#define T_DIM    128
#define DEG      5
#define BT       (B_DIM * T_DIM)          // 16384 nodes
#define E_EDGES  (BT * DEG)               // 81920
#define WSZ      (U_DIM * U_DIM)          // 65536 floats per weight matrix

// ---------------------------------------------------------------------------
// Scratch (device globals — no allocation allowed)
// ---------------------------------------------------------------------------
__device__ float g_X0[BT * U_DIM];
__device__ float g_X1[BT * U_DIM];
__device__ float g_Xtf[BT * U_DIM];               // tf32-rounded copy of X
__device__ float g_Wtf[L_LAYERS * 3 * WSZ];       // tf32-rounded weights
__device__ float g_XVin[BT * U_DIM];
__device__ float g_XVout[BT * U_DIM];
__device__ float g_XVloop[BT * U_DIM];
__device__ float g_gin[BT];
__device__ float g_gout[BT];
__device__ float g_gloop[BT];
__device__ float g_enc[B_DIM * U_DIM];

// ---------------------------------------------------------------------------
// helpers
// ---------------------------------------------------------------------------
__device__ __forceinline__ uint32_t f2tf32(float f) {
    uint32_t r;
    asm("cvt.rna.tf32.f32 %0, %1;" : "=r"(r) : "f"(f));
    return r;
}

__device__ __forceinline__ float4 cvt4(float4 v) {
    float4 o;
    o.x = __uint_as_float(f2tf32(v.x));
    o.y = __uint_as_float(f2tf32(v.y));
    o.z = __uint_as_float(f2tf32(v.z));
    o.w = __uint_as_float(f2tf32(v.w));
    return o;
}

__device__ __forceinline__ void mma_tf32(float* d, const uint32_t* a,
                                         const uint32_t* b) {
    asm volatile(
        "mma.sync.aligned.m16n8k8.row.col.f32.tf32.tf32.f32 "
        "{%0,%1,%2,%3}, {%4,%5,%6,%7}, {%8,%9}, {%0,%1,%2,%3};\n"
        : "+f"(d[0]), "+f"(d[1]), "+f"(d[2]), "+f"(d[3])
        : "r"(a[0]), "r"(a[1]), "r"(a[2]), "r"(a[3]), "r"(b[0]), "r"(b[1]));
}

__device__ __forceinline__ void cp16(void* dst, const void* src) {
    uint32_t d = (uint32_t)__cvta_generic_to_shared(dst);
    asm volatile("cp.async.cg.shared.global [%0], [%1], 16;\n"
                 :: "r"(d), "l"(src));
}
#define CP_COMMIT() asm volatile("cp.async.commit_group;\n" ::: "memory")
#define CP_WAIT1()  asm volatile("cp.async.wait_group 1;\n" ::: "memory")

// ---------------------------------------------------------------------------
// 0) Weight conversion: all L*3 weight matrices -> tf32 bits, once.
// ---------------------------------------------------------------------------
__global__ void cvtw_k(const float* __restrict__ Vin,
                       const float* __restrict__ Vout,
                       const float* __restrict__ Wloop,
                       float* __restrict__ out)
{
    int idx = blockIdx.x * 256 + threadIdx.x;     // float4 index
    int l   = idx / (3 * WSZ / 4);
    int r   = idx % (3 * WSZ / 4);
    int sel = r / (WSZ / 4);
    int e4  = r % (WSZ / 4);
    const float* src = (sel == 0) ? Vin : ((sel == 1) ? Vout : Wloop);
    float4 v = reinterpret_cast<const float4*>(src + (size_t)l * WSZ)[e4];
    reinterpret_cast<float4*>(out)[idx] = cvt4(v);
}

// ---------------------------------------------------------------------------
// 1) Embedding gather: X[n=b*T+t] = emb[src[t,b]]; also tf32 copy.
// ---------------------------------------------------------------------------
__global__ void embed_k(const int* __restrict__ src,
                        const float* __restrict__ emb,
                        float* __restrict__ X,
                        float* __restrict__ Xtf)
{
    int grp = threadIdx.x >> 6;
    int n   = blockIdx.x * 4 + grp;
    int lu  = threadIdx.x & 63;
    int b = n / T_DIM, t = n % T_DIM;
    int tok = src[t * B_DIM + b];
    float4 v = reinterpret_cast<const float4*>(emb)[(size_t)tok * U4 + lu];
    reinterpret_cast<float4*>(X)[(size_t)n * U4 + lu]   = v;
    reinterpret_cast<float4*>(Xtf)[(size_t)n * U4 + lu] = cvt4(v);
}

// ---------------------------------------------------------------------------
// 2) Fused TF32 GEMM + gates.
//    grid(128, 7), 512 threads:
//      y in [0,6): C = Atf * Wtf[sel]; (y&1)*128 picks N half.
//                  128x128 tile, BK=16, 2-stage cp.async (37.9KB smem),
//                  16 warps (4M x 4N), warp tile 32x32, 2 CTAs/SM.
//      y == 6   : gate GEMVs on ORIGINAL A (full fp32 precision).
// ---------------------------------------------------------------------------
#define GBM 128
#define GBN 128
#define GBK 16
#define NT  (U_DIM / GBK)     // 16 k-tiles
#define GTHREADS 512

__global__ __launch_bounds__(GTHREADS, 2)
void gemm_gate_k(const float* __restrict__ Atf,
                 const float* __restrict__ Wtf,   // [3][WSZ] for this layer
                 float* __restrict__ C0, float* __restrict__ C1,
                 float* __restrict__ C2,
                 const float* __restrict__ Aorig,
                 const float* __restrict__ vgin,
                 const float* __restrict__ vgout,
                 const float* __restrict__ wgl,
                 float* __restrict__ gin, float* __restrict__ gout,
                 float* __restrict__ gloop)
{
    // ---------------- gate slice ----------------
    if (blockIdx.y == 6) {
        int warp = threadIdx.x >> 5;        // 0..15
        int lane = threadIdx.x & 31;
        const float4* v0 = reinterpret_cast<const float4*>(vgin);
        const float4* v1 = reinterpret_cast<const float4*>(vgout);
        const float4* v2 = reinterpret_cast<const float4*>(wgl);
#pragma unroll 1
        for (int i = 0; i < 8; i++) {
            int n = blockIdx.x * 128 + i * 16 + warp;
            const float4* xr =
                reinterpret_cast<const float4*>(Aorig + (size_t)n * U_DIM);
            float s0 = 0.f, s1 = 0.f, s2 = 0.f;
#pragma unroll
            for (int k = lane; k < U4; k += 32) {
                float4 x = xr[k];
                float4 a = v0[k], b = v1[k], c = v2[k];
                s0 += x.x * a.x + x.y * a.y + x.z * a.z + x.w * a.w;
                s1 += x.x * b.x + x.y * b.y + x.z * b.z + x.w * b.w;
                s2 += x.x * c.x + x.y * c.y + x.z * c.z + x.w * c.w;
            }
#pragma unroll
            for (int off = 16; off > 0; off >>= 1) {
                s0 += __shfl_down_sync(0xffffffffu, s0, off);
                s1 += __shfl_down_sync(0xffffffffu, s1, off);
                s2 += __shfl_down_sync(0xffffffffu, s2, off);
            }
            if (lane == 0) { gin[n] = s0; gout[n] = s1; gloop[n] = s2; }
        }
        return;
    }

    // ---------------- GEMM slice ----------------
    const int sel     = blockIdx.y >> 1;
    const int colbase = (blockIdx.y & 1) * GBN;
    const float* __restrict__ W = Wtf + (size_t)sel * WSZ;
    float* __restrict__ C       = (sel == 0) ? C0 : ((sel == 1) ? C1 : C2);
    const int mbase = blockIdx.x * GBM;

    // As pitch 20 / Bs pitch 136 -> conflict-free fragment LDS.
    // 2 stages: 2*(128*20 + 16*136)*4 = 37,888 B (< 48KB static cap)
    __shared__ __align__(16) float As[2][GBM][GBK + 4];
    __shared__ __align__(16) float Bs[2][GBK][GBN + 8];

    const int tid  = threadIdx.x;
    const int lane = tid & 31;
    const int warp = tid >> 5;
    const int wm   = (warp & 3) * 32;          // warp M offset
    const int wn   = (warp >> 2) * 32;         // warp N offset
    const int g    = lane >> 2;                // 0..7
    const int t    = lane & 3;                 // 0..3

    // cp.async: exactly one 16B per thread per operand per tile
    const int aRow = tid >> 2;                 // 0..127
    const int aK4  = (tid & 3) * 4;            // 0,4,8,12
    const int bK   = tid >> 5;                 // 0..15
    const int bN4  = (tid & 31) * 4;           // 0..124

    const float* Abase = Atf + (size_t)(mbase + aRow) * U_DIM + aK4;
    const float* Wbase = W + (size_t)bK * U_DIM + colbase + bN4;

    float acc[2][4][4];
#pragma unroll
    for (int mi = 0; mi < 2; mi++)
#pragma unroll
        for (int ni = 0; ni < 4; ni++)
#pragma unroll
            for (int c = 0; c < 4; c++) acc[mi][ni][c] = 0.f;

    // prologue: tile 0 into stage 0
    cp16(&As[0][aRow][aK4], Abase);
    cp16(&Bs[0][bK][bN4],   Wbase);
    CP_COMMIT();

    for (int tile = 0; tile < NT; tile++) {
        int nxt = tile + 1;
        if (nxt < NT) {
            int s  = nxt & 1;
            int k0 = nxt * GBK;
            cp16(&As[s][aRow][aK4], Abase + k0);
            cp16(&Bs[s][bK][bN4],   Wbase + (size_t)k0 * U_DIM);
        }
        CP_COMMIT();
        CP_WAIT1();        // current tile's group complete
        __syncthreads();

        const int st = tile & 1;
#pragma unroll
        for (int ks = 0; ks < GBK; ks += 8) {
            uint32_t afr[2][4];
#pragma unroll
            for (int mi = 0; mi < 2; mi++) {
                int m0 = wm + mi * 16;
                afr[mi][0] = __float_as_uint(As[st][m0 + g][ks + t]);
                afr[mi][1] = __float_as_uint(As[st][m0 + g + 8][ks + t]);
                afr[mi][2] = __float_as_uint(As[st][m0 + g][ks + t + 4]);
                afr[mi][3] = __float_as_uint(As[st][m0 + g + 8][ks + t + 4]);
            }
            uint32_t bfr[4][2];
#pragma unroll
            for (int ni = 0; ni < 4; ni++) {
                int n0 = wn + ni * 8 + g;
                bfr[ni][0] = __float_as_uint(Bs[st][ks + t][n0]);
                bfr[ni][1] = __float_as_uint(Bs[st][ks + t + 4][n0]);
            }
#pragma unroll
            for (int mi = 0; mi < 2; mi++)
#pragma unroll
                for (int ni = 0; ni < 4; ni++)
                    mma_tf32(acc[mi][ni], afr[mi], bfr[ni]);
        }
        __syncthreads();   // all warps done with this stage before overwrite
    }

    // epilogue
#pragma unroll
    for (int mi = 0; mi < 2; mi++) {
#pragma unroll
        for (int ni = 0; ni < 4; ni++) {
            int row = mbase + wm + mi * 16 + g;
            int col = colbase + wn + ni * 8 + 2 * t;
            float2 v0 = make_float2(acc[mi][ni][0], acc[mi][ni][1]);
            float2 v1 = make_float2(acc[mi][ni][2], acc[mi][ni][3]);
            *reinterpret_cast<float2*>(&C[(size_t)row * U_DIM + col])       = v0;
            *reinterpret_cast<float2*>(&C[(size_t)(row + 8) * U_DIM + col]) = v1;
        }
    }
}

// ---------------------------------------------------------------------------
// 3) Edge aggregation, float4: 64 threads/node, 4 nodes/block.
// ---------------------------------------------------------------------------
__global__ __launch_bounds__(256)
void agg_k(const float* __restrict__ XVin,
           const float* __restrict__ XVout,
           const float* __restrict__ XVloop,
           const float* __restrict__ gin,
           const float* __restrict__ gout,
           const float* __restrict__ gloop,
           const int* __restrict__ arc_in,
           const int* __restrict__ arc_out,
           const int* __restrict__ lab_in,
           const int* __restrict__ lab_out,
           const float* __restrict__ b_in,
           const float* __restrict__ bg_in,
           const float* __restrict__ b_out,
           const float* __restrict__ bg_out,
           const float* __restrict__ mask_in,
           const float* __restrict__ mask_out,
           const float* __restrict__ mask_loop,
           const float* __restrict__ sent_mask,
           float* __restrict__ Y, float* __restrict__ Ytf, int tb_layout)
{
    int grp = threadIdx.x >> 6;
    int n   = blockIdx.x * 4 + grp;
    int lu  = threadIdx.x & 63;

    __shared__ float p_in[4][DEG], p_out[4][DEG], p_loop[4];
    __shared__ int   s_in[4][DEG], s_out[4][DEG], l_in[4][DEG], l_out[4][DEG];

    if (lu < DEG) {
        int d = lu, e = n * DEG + d;
        int si = arc_in[e] * T_DIM + arc_in[E_EDGES + e];
        int li = lab_in[e];
        float gi = gin[si] + bg_in[li];
        p_in[grp][d] = (1.f / (1.f + __expf(-gi))) * mask_in[n * DEG + d];
        s_in[grp][d] = si; l_in[grp][d] = li;
    } else if (lu < 2 * DEG) {
        int d = lu - DEG, e = n * DEG + d;
        int so = arc_out[e] * T_DIM + arc_out[E_EDGES + e];
        int lo = lab_out[e];
        float go = gout[so] + bg_out[lo];
        p_out[grp][d] = (1.f / (1.f + __expf(-go))) * mask_out[n * DEG + d];
        s_out[grp][d] = so; l_out[grp][d] = lo;
    } else if (lu == 2 * DEG) {
        p_loop[grp] = (1.f / (1.f + __expf(-gloop[n]))) * mask_loop[n];
    }
    __syncthreads();

    const float4* XVin4   = reinterpret_cast<const float4*>(XVin);
    const float4* XVout4  = reinterpret_cast<const float4*>(XVout);
    const float4* XVloop4 = reinterpret_cast<const float4*>(XVloop);
    const float4* bin4    = reinterpret_cast<const float4*>(b_in);
    const float4* bout4   = reinterpret_cast<const float4*>(b_out);

    float pl = p_loop[grp];
    float4 h = XVloop4[(size_t)n * U4 + lu];
    float4 acc = make_float4(pl * h.x, pl * h.y, pl * h.z, pl * h.w);

#pragma unroll
    for (int d = 0; d < DEG; d++) {
        float p = p_in[grp][d];
        float4 v = XVin4[(size_t)s_in[grp][d] * U4 + lu];
        float4 bb = bin4[(size_t)l_in[grp][d] * U4 + lu];
        acc.x = fmaf(p, v.x + bb.x, acc.x);
        acc.y = fmaf(p, v.y + bb.y, acc.y);
        acc.z = fmaf(p, v.z + bb.z, acc.z);
        acc.w = fmaf(p, v.w + bb.w, acc.w);
        p = p_out[grp][d];
        v = XVout4[(size_t)s_out[grp][d] * U4 + lu];
        bb = bout4[(size_t)l_out[grp][d] * U4 + lu];
        acc.x = fmaf(p, v.x + bb.x, acc.x);
        acc.y = fmaf(p, v.y + bb.y, acc.y);
        acc.z = fmaf(p, v.z + bb.z, acc.z);
        acc.w = fmaf(p, v.w + bb.w, acc.w);
    }
    int b = n / T_DIM, t = n % T_DIM;
    float sm = sent_mask[t * B_DIM + b];
    acc.x = fmaxf(acc.x, 0.f) * sm;
    acc.y = fmaxf(acc.y, 0.f) * sm;
    acc.z = fmaxf(acc.z, 0.f) * sm;
    acc.w = fmaxf(acc.w, 0.f) * sm;
    size_t oidx = tb_layout ? ((size_t)t * B_DIM + b) * U4 + lu
                            : (size_t)n * U4 + lu;
    reinterpret_cast<float4*>(Y)[oidx] = acc;
    if (Ytf)
        reinterpret_cast<float4*>(Ytf)[(size_t)n * U4 + lu] = cvt4(acc);
}

// ---------------------------------------------------------------------------
// 4) enc[b] from membank layout
// ---------------------------------------------------------------------------
__global__ void enc_k(const float* __restrict__ MB,
                      const float* __restrict__ sent_mask,
                      float* __restrict__ enc)
{
    int b = blockIdx.x;
    int u = threadIdx.x;  // 0..63
    const float4* M4 = reinterpret_cast<const float4*>(MB);
    float4 s = make_float4(0.f, 0.f, 0.f, 0.f);
#pragma unroll 4
    for (int t = 0; t < T_DIM; t++) {
        float4 v = M4[((size_t)t * B_DIM + b) * U4 + u];
        s.x += v.x; s.y += v.y; s.z += v.z; s.w += v.w;
    }
    __shared__ float ms;
    if (u == 0) {
        float m = 0.f;
        for (int t = 0; t < T_DIM; t++) m += sent_mask[t * B_DIM + b];
        ms = m;
    }
    __syncthreads();
    float inv = 1.f / ms;
    s.x *= inv; s.y *= inv; s.z *= inv; s.w *= inv;
    reinterpret_cast<float4*>(enc)[b * U4 + u] = s;
}

// ---------------------------------------------------------------------------
// 5) h_all[k,b,w] = sum_u enc[b,u] * H[k,u,w]
// ---------------------------------------------------------------------------
__global__ void hall_k(const float* __restrict__ enc,
                       const float* __restrict__ H,
                       float* __restrict__ out)
{
    int k = blockIdx.y, b = blockIdx.x, w = threadIdx.x;
    __shared__ float es[U_DIM];
    es[w] = enc[b * U_DIM + w];
    __syncthreads();
    const float* Hk = H + (size_t)k * U_DIM * U_DIM;
    float acc = 0.f;
#pragma unroll 8
    for (int u = 0; u < U_DIM; u++)
        acc = fmaf(es[u], Hk[u * U_DIM + w], acc);
    out[((size_t)k * B_DIM + b) * U_DIM + w] = acc;
}

// ---------------------------------------------------------------------------
// Launch
// ---------------------------------------------------------------------------
extern "C" void kernel_launch(void* const* d_in, const int* in_sizes, int n_in,
                              void* d_out, int out_size)
{
    const int*   src       = (const int*)  d_in[0];
    const int*   arc_in    = (const int*)  d_in[1];
    const int*   arc_out   = (const int*)  d_in[2];
    const int*   lab_in    = (const int*)  d_in[3];
    const int*   lab_out   = (const int*)  d_in[4];
    const float* mask_in   = (const float*)d_in[5];
    const float* mask_out  = (const float*)d_in[6];
    const float* mask_loop = (const float*)d_in[7];
    const float* sent_mask = (const float*)d_in[8];
    const float* emb       = (const float*)d_in[9];
    const float* V_in      = (const float*)d_in[10];
    const float* b_in      = (const float*)d_in[11];
    const float* Vg_in     = (const float*)d_in[12];
    const float* bg_in     = (const float*)d_in[13];
    const float* V_out     = (const float*)d_in[14];
    const float* b_out     = (const float*)d_in[15];
    const float* Vg_out    = (const float*)d_in[16];
    const float* bg_out    = (const float*)d_in[17];
    const float* W_loop    = (const float*)d_in[18];
    const float* Wg_loop   = (const float*)d_in[19];
    const float* H         = (const float*)d_in[20];
    float* out = (float*)d_out;

    float *pX0, *pX1, *pXtf, *pWtf, *pXVin, *pXVout, *pXVloop;
    float *pgin, *pgout, *pgloop, *penc;
    cudaGetSymbolAddress((void**)&pX0,     g_X0);
    cudaGetSymbolAddress((void**)&pX1,     g_X1);
    cudaGetSymbolAddress((void**)&pXtf,    g_Xtf);
    cudaGetSymbolAddress((void**)&pWtf,    g_Wtf);
    cudaGetSymbolAddress((void**)&pXVin,   g_XVin);
    cudaGetSymbolAddress((void**)&pXVout,  g_XVout);
    cudaGetSymbolAddress((void**)&pXVloop, g_XVloop);
    cudaGetSymbolAddress((void**)&pgin,    g_gin);
    cudaGetSymbolAddress((void**)&pgout,   g_gout);
    cudaGetSymbolAddress((void**)&pgloop,  g_gloop);
    cudaGetSymbolAddress((void**)&penc,    g_enc);

    float* memOut = out + 4 * B_DIM * U_DIM;   // membank region of d_out

    cvtw_k<<<L_LAYERS * 3 * WSZ / 4 / 256, 256>>>(V_in, V_out, W_loop, pWtf);
    embed_k<<<BT / 4, 256>>>(src, emb, pX0, pXtf);

    float* Xcur = pX0;
    for (int l = 0; l < L_LAYERS; l++) {
        const size_t gOff  = (size_t)l * U_DIM;
        const size_t bOff  = (size_t)l * NL_LAB * U_DIM;
        const size_t bgOff = (size_t)l * NL_LAB;
        const int last = (l == L_LAYERS - 1);

        dim3 ggrid(BT / GBM, 7);
        gemm_gate_k<<<ggrid, GTHREADS>>>(pXtf, pWtf + (size_t)l * 3 * WSZ,
                                         pXVin, pXVout, pXVloop,
                                         Xcur,
                                         Vg_in + gOff, Vg_out + gOff,
                                         Wg_loop + gOff,
                                         pgin, pgout, pgloop);
        agg_k<<<BT / 4, 256>>>(pXVin, pXVout, pXVloop, pgin, pgout, pgloop,
                               arc_in, arc_out, lab_in, lab_out,
                               b_in + bOff, bg_in + bgOff,
                               b_out + bOff, bg_out + bgOff,
                               mask_in, mask_out, mask_loop, sent_mask,
                               last ? memOut : pX1,
                               last ? nullptr : pXtf,
                               last ? 1 : 0);
        Xcur = pX1;
    }

    enc_k<<<B_DIM, 64>>>(memOut, sent_mask, penc);
    hall_k<<<dim3(B_DIM, 4), U_DIM>>>(penc, H, out);
}

// round 9
// speedup vs baseline: 2.7434x; 1.0171x over previous
#include <cuda_runtime.h>
#include <cuda_bf16.h>
#include <cstdint>

// Problem constants
#define L_LAYERS 2
#define U_DIM    256
#define U4       (U_DIM / 4)
#define NL_LAB   64
#define B_DIM    128
#define T_DIM    128
#define DEG      5
#define BT       (B_DIM * T_DIM)          // 16384 nodes
#define E_EDGES  (BT * DEG)               // 81920
#define WSZ      (U_DIM * U_DIM)          // 65536 floats per weight matrix

// ---------------------------------------------------------------------------
// Scratch (device globals — no allocation allowed)
// ---------------------------------------------------------------------------
__device__ float g_X0[BT * U_DIM];
__device__ float g_X1[BT * U_DIM];
__device__ float g_Xtf[BT * U_DIM];               // tf32-rounded copy of X
__device__ float g_Wtf[L_LAYERS * 3 * WSZ];       // tf32-rounded weights [l][sel][K][N]
__device__ float g_XVin[BT * U_DIM];
__device__ float g_XVout[BT * U_DIM];
__device__ float g_XVloop[BT * U_DIM];
__device__ float g_gin[BT];
__device__ float g_gout[BT];
__device__ float g_gloop[BT];
__device__ float g_enc[B_DIM * U_DIM];

// ---------------------------------------------------------------------------
// helpers
// ---------------------------------------------------------------------------
__device__ __forceinline__ uint32_t f2tf32(float f) {
    uint32_t r;
    asm("cvt.rna.tf32.f32 %0, %1;" : "=r"(r) : "f"(f));
    return r;
}

__device__ __forceinline__ float4 cvt4(float4 v) {
    float4 o;
    o.x = __uint_as_float(f2tf32(v.x));
    o.y = __uint_as_float(f2tf32(v.y));
    o.z = __uint_as_float(f2tf32(v.z));
    o.w = __uint_as_float(f2tf32(v.w));
    return o;
}

__device__ __forceinline__ void mma_tf32(float* d, const uint32_t* a,
                                         const uint32_t* b) {
    asm volatile(
        "mma.sync.aligned.m16n8k8.row.col.f32.tf32.tf32.f32 "
        "{%0,%1,%2,%3}, {%4,%5,%6,%7}, {%8,%9}, {%0,%1,%2,%3};\n"
        : "+f"(d[0]), "+f"(d[1]), "+f"(d[2]), "+f"(d[3])
        : "r"(a[0]), "r"(a[1]), "r"(a[2]), "r"(a[3]), "r"(b[0]), "r"(b[1]));
}

__device__ __forceinline__ void cp16(void* dst, const void* src) {
    uint32_t d = (uint32_t)__cvta_generic_to_shared(dst);
    asm volatile("cp.async.cg.shared.global [%0], [%1], 16;\n"
                 :: "r"(d), "l"(src));
}
#define CP_COMMIT() asm volatile("cp.async.commit_group;\n" ::: "memory")
#define CP_WAIT1()  asm volatile("cp.async.wait_group 1;\n" ::: "memory")
#define CP_WAIT0()  asm volatile("cp.async.wait_group 0;\n" ::: "memory")

// ---------------------------------------------------------------------------
// 0) Weight conversion: all L*3 weight matrices -> tf32 bits, once.
// ---------------------------------------------------------------------------
__global__ void cvtw_k(const float* __restrict__ Vin,
                       const float* __restrict__ Vout,
                       const float* __restrict__ Wloop,
                       float* __restrict__ out)
{
    int idx = blockIdx.x * 256 + threadIdx.x;     // float4 index
    int l   = idx / (3 * WSZ / 4);
    int r   = idx % (3 * WSZ / 4);
    int sel = r / (WSZ / 4);
    int e4  = r % (WSZ / 4);
    const float* src = (sel == 0) ? Vin : ((sel == 1) ? Vout : Wloop);
    float4 v = reinterpret_cast<const float4*>(src + (size_t)l * WSZ)[e4];
    reinterpret_cast<float4*>(out)[idx] = cvt4(v);
}

// ---------------------------------------------------------------------------
// 1) Embedding gather: X[n=b*T+t] = emb[src[t,b]]; also tf32 copy.
// ---------------------------------------------------------------------------
__global__ void embed_k(const int* __restrict__ src,
                        const float* __restrict__ emb,
                        float* __restrict__ X,
                        float* __restrict__ Xtf)
{
    int grp = threadIdx.x >> 6;
    int n   = blockIdx.x * 4 + grp;
    int lu  = threadIdx.x & 63;
    int b = n / T_DIM, t = n % T_DIM;
    int tok = src[t * B_DIM + b];
    float4 v = reinterpret_cast<const float4*>(emb)[(size_t)tok * U4 + lu];
    reinterpret_cast<float4*>(X)[(size_t)n * U4 + lu]   = v;
    reinterpret_cast<float4*>(Xtf)[(size_t)n * U4 + lu] = cvt4(v);
}

// ---------------------------------------------------------------------------
// 2) Fused TF32 GEMM + gates.
//    grid(128, 7), 512 threads, dynamic smem:
//      y in [0,6): C = Atf * Wtf[sel]; (y&1)*128 picks N half.
//                  128x128 tile, BK=16, 3-stage cp.async (56.8KB dyn smem),
//                  ONE barrier per tile, 16 warps (4M x 4N), warp tile 32x32,
//                  2 CTAs/SM (113.7KB < 227KB).
//      y == 6   : gate GEMVs on ORIGINAL A (full fp32 precision).
// ---------------------------------------------------------------------------
#define GBM 128
#define GBN 128
#define GBK 16
#define NT  (U_DIM / GBK)     // 16 k-tiles
#define GTHREADS 512
#define A_STAGE_F (GBM * (GBK + 4))     // 2560 floats
#define B_STAGE_F (GBK * (GBN + 8))     // 2176 floats
#define SMEM_DYN  (3 * (A_STAGE_F + B_STAGE_F) * 4)   // 56,832 B

__global__ __launch_bounds__(GTHREADS, 2)
void gemm_gate_k(const float* __restrict__ Atf,
                 const float* __restrict__ Wtf,   // [3][WSZ] for this layer
                 float* __restrict__ C0, float* __restrict__ C1,
                 float* __restrict__ C2,
                 const float* __restrict__ Aorig,
                 const float* __restrict__ vgin,
                 const float* __restrict__ vgout,
                 const float* __restrict__ wgl,
                 float* __restrict__ gin, float* __restrict__ gout,
                 float* __restrict__ gloop)
{
    // ---------------- gate slice ----------------
    if (blockIdx.y == 6) {
        int warp = threadIdx.x >> 5;        // 0..15
        int lane = threadIdx.x & 31;
        const float4* v0 = reinterpret_cast<const float4*>(vgin);
        const float4* v1 = reinterpret_cast<const float4*>(vgout);
        const float4* v2 = reinterpret_cast<const float4*>(wgl);
#pragma unroll 1
        for (int i = 0; i < 8; i++) {
            int n = blockIdx.x * 128 + i * 16 + warp;
            const float4* xr =
                reinterpret_cast<const float4*>(Aorig + (size_t)n * U_DIM);
            float s0 = 0.f, s1 = 0.f, s2 = 0.f;
#pragma unroll
            for (int k = lane; k < U4; k += 32) {
                float4 x = xr[k];
                float4 a = v0[k], b = v1[k], c = v2[k];
                s0 += x.x * a.x + x.y * a.y + x.z * a.z + x.w * a.w;
                s1 += x.x * b.x + x.y * b.y + x.z * b.z + x.w * b.w;
                s2 += x.x * c.x + x.y * c.y + x.z * c.z + x.w * c.w;
            }
#pragma unroll
            for (int off = 16; off > 0; off >>= 1) {
                s0 += __shfl_down_sync(0xffffffffu, s0, off);
                s1 += __shfl_down_sync(0xffffffffu, s1, off);
                s2 += __shfl_down_sync(0xffffffffu, s2, off);
            }
            if (lane == 0) { gin[n] = s0; gout[n] = s1; gloop[n] = s2; }
        }
        return;
    }

    // ---------------- GEMM slice ----------------
    const int sel     = blockIdx.y >> 1;
    const int colbase = (blockIdx.y & 1) * GBN;
    const float* __restrict__ W = Wtf + (size_t)sel * WSZ;
    float* __restrict__ C       = (sel == 0) ? C0 : ((sel == 1) ? C1 : C2);
    const int mbase = blockIdx.x * GBM;

    // dynamic smem: 3-stage A and B tiles
    extern __shared__ __align__(16) float dsm[];
    float (*As)[GBM][GBK + 4] =
        reinterpret_cast<float (*)[GBM][GBK + 4]>(dsm);
    float (*Bs)[GBK][GBN + 8] =
        reinterpret_cast<float (*)[GBK][GBN + 8]>(dsm + 3 * A_STAGE_F);

    const int tid  = threadIdx.x;
    const int lane = tid & 31;
    const int warp = tid >> 5;
    const int wm   = (warp & 3) * 32;          // warp M offset
    const int wn   = (warp >> 2) * 32;         // warp N offset
    const int g    = lane >> 2;                // 0..7
    const int t    = lane & 3;                 // 0..3

    // cp.async: exactly one 16B per thread per operand per tile
    const int aRow = tid >> 2;                 // 0..127
    const int aK4  = (tid & 3) * 4;            // 0,4,8,12
    const int bK   = tid >> 5;                 // 0..15
    const int bN4  = (tid & 31) * 4;           // 0..124

    const float* Abase = Atf + (size_t)(mbase + aRow) * U_DIM + aK4;
    const float* Wbase = W + (size_t)bK * U_DIM + colbase + bN4;

    float acc[2][4][4];
#pragma unroll
    for (int mi = 0; mi < 2; mi++)
#pragma unroll
        for (int ni = 0; ni < 4; ni++)
#pragma unroll
            for (int c = 0; c < 4; c++) acc[mi][ni][c] = 0.f;

    // prologue: tiles 0 and 1 into stages 0 and 1
    cp16(&As[0][aRow][aK4], Abase);
    cp16(&Bs[0][bK][bN4],   Wbase);
    CP_COMMIT();
    cp16(&As[1][aRow][aK4], Abase + GBK);
    cp16(&Bs[1][bK][bN4],   Wbase + (size_t)GBK * U_DIM);
    CP_COMMIT();

#pragma unroll 1
    for (int tile = 0; tile < NT; tile++) {
        if (tile < NT - 1) { CP_WAIT1(); } else { CP_WAIT0(); }
        __syncthreads();   // single barrier: tile data visible, stage (tile+2)%3 free

        int nxt = tile + 2;
        if (nxt < NT) {
            int s  = nxt % 3;
            int k0 = nxt * GBK;
            cp16(&As[s][aRow][aK4], Abase + k0);
            cp16(&Bs[s][bK][bN4],   Wbase + (size_t)k0 * U_DIM);
            CP_COMMIT();
        }

        const int st = tile % 3;
#pragma unroll
        for (int ks = 0; ks < GBK; ks += 8) {
            uint32_t afr[2][4];
#pragma unroll
            for (int mi = 0; mi < 2; mi++) {
                int m0 = wm + mi * 16;
                afr[mi][0] = __float_as_uint(As[st][m0 + g][ks + t]);
                afr[mi][1] = __float_as_uint(As[st][m0 + g + 8][ks + t]);
                afr[mi][2] = __float_as_uint(As[st][m0 + g][ks + t + 4]);
                afr[mi][3] = __float_as_uint(As[st][m0 + g + 8][ks + t + 4]);
            }
            uint32_t bfr[4][2];
#pragma unroll
            for (int ni = 0; ni < 4; ni++) {
                int n0 = wn + ni * 8 + g;
                bfr[ni][0] = __float_as_uint(Bs[st][ks + t][n0]);
                bfr[ni][1] = __float_as_uint(Bs[st][ks + t + 4][n0]);
            }
#pragma unroll
            for (int mi = 0; mi < 2; mi++)
#pragma unroll
                for (int ni = 0; ni < 4; ni++)
                    mma_tf32(acc[mi][ni], afr[mi], bfr[ni]);
        }
    }

    // epilogue
#pragma unroll
    for (int mi = 0; mi < 2; mi++) {
#pragma unroll
        for (int ni = 0; ni < 4; ni++) {
            int row = mbase + wm + mi * 16 + g;
            int col = colbase + wn + ni * 8 + 2 * t;
            float2 v0 = make_float2(acc[mi][ni][0], acc[mi][ni][1]);
            float2 v1 = make_float2(acc[mi][ni][2], acc[mi][ni][3]);
            *reinterpret_cast<float2*>(&C[(size_t)row * U_DIM + col])       = v0;
            *reinterpret_cast<float2*>(&C[(size_t)(row + 8) * U_DIM + col]) = v1;
        }
    }
}

// ---------------------------------------------------------------------------
// 3) Edge aggregation, float4: 64 threads/node, 4 nodes/block.
// ---------------------------------------------------------------------------
__global__ __launch_bounds__(256)
void agg_k(const float* __restrict__ XVin,
           const float* __restrict__ XVout,
           const float* __restrict__ XVloop,
           const float* __restrict__ gin,
           const float* __restrict__ gout,
           const float* __restrict__ gloop,
           const int* __restrict__ arc_in,
           const int* __restrict__ arc_out,
           const int* __restrict__ lab_in,
           const int* __restrict__ lab_out,
           const float* __restrict__ b_in,
           const float* __restrict__ bg_in,
           const float* __restrict__ b_out,
           const float* __restrict__ bg_out,
           const float* __restrict__ mask_in,
           const float* __restrict__ mask_out,
           const float* __restrict__ mask_loop,
           const float* __restrict__ sent_mask,
           float* __restrict__ Y, float* __restrict__ Ytf, int tb_layout)
{
    int grp = threadIdx.x >> 6;
    int n   = blockIdx.x * 4 + grp;
    int lu  = threadIdx.x & 63;

    __shared__ float p_in[4][DEG], p_out[4][DEG], p_loop[4];
    __shared__ int   s_in[4][DEG], s_out[4][DEG], l_in[4][DEG], l_out[4][DEG];

    if (lu < DEG) {
        int d = lu, e = n * DEG + d;
        int si = arc_in[e] * T_DIM + arc_in[E_EDGES + e];
        int li = lab_in[e];
        float gi = gin[si] + bg_in[li];
        p_in[grp][d] = (1.f / (1.f + __expf(-gi))) * mask_in[n * DEG + d];
        s_in[grp][d] = si; l_in[grp][d] = li;
    } else if (lu < 2 * DEG) {
        int d = lu - DEG, e = n * DEG + d;
        int so = arc_out[e] * T_DIM + arc_out[E_EDGES + e];
        int lo = lab_out[e];
        float go = gout[so] + bg_out[lo];
        p_out[grp][d] = (1.f / (1.f + __expf(-go))) * mask_out[n * DEG + d];
        s_out[grp][d] = so; l_out[grp][d] = lo;
    } else if (lu == 2 * DEG) {
        p_loop[grp] = (1.f / (1.f + __expf(-gloop[n]))) * mask_loop[n];
    }
    __syncthreads();

    const float4* XVin4   = reinterpret_cast<const float4*>(XVin);
    const float4* XVout4  = reinterpret_cast<const float4*>(XVout);
    const float4* XVloop4 = reinterpret_cast<const float4*>(XVloop);
    const float4* bin4    = reinterpret_cast<const float4*>(b_in);
    const float4* bout4   = reinterpret_cast<const float4*>(b_out);

    float pl = p_loop[grp];
    float4 h = XVloop4[(size_t)n * U4 + lu];
    float4 acc = make_float4(pl * h.x, pl * h.y, pl * h.z, pl * h.w);

#pragma unroll
    for (int d = 0; d < DEG; d++) {
        float p = p_in[grp][d];
        float4 v = XVin4[(size_t)s_in[grp][d] * U4 + lu];
        float4 bb = bin4[(size_t)l_in[grp][d] * U4 + lu];
        acc.x = fmaf(p, v.x + bb.x, acc.x);
        acc.y = fmaf(p, v.y + bb.y, acc.y);
        acc.z = fmaf(p, v.z + bb.z, acc.z);
        acc.w = fmaf(p, v.w + bb.w, acc.w);
        p = p_out[grp][d];
        v = XVout4[(size_t)s_out[grp][d] * U4 + lu];
        bb = bout4[(size_t)l_out[grp][d] * U4 + lu];
        acc.x = fmaf(p, v.x + bb.x, acc.x);
        acc.y = fmaf(p, v.y + bb.y, acc.y);
        acc.z = fmaf(p, v.z + bb.z, acc.z);
        acc.w = fmaf(p, v.w + bb.w, acc.w);
    }
    int b = n / T_DIM, t = n % T_DIM;
    float sm = sent_mask[t * B_DIM + b];
    acc.x = fmaxf(acc.x, 0.f) * sm;
    acc.y = fmaxf(acc.y, 0.f) * sm;
    acc.z = fmaxf(acc.z, 0.f) * sm;
    acc.w = fmaxf(acc.w, 0.f) * sm;
    size_t oidx = tb_layout ? ((size_t)t * B_DIM + b) * U4 + lu
                            : (size_t)n * U4 + lu;
    reinterpret_cast<float4*>(Y)[oidx] = acc;
    if (Ytf)
        reinterpret_cast<float4*>(Ytf)[(size_t)n * U4 + lu] = cvt4(acc);
}

// ---------------------------------------------------------------------------
// 4) enc[b] from membank layout
// ---------------------------------------------------------------------------
__global__ void enc_k(const float* __restrict__ MB,
                      const float* __restrict__ sent_mask,
                      float* __restrict__ enc)
{
    int b = blockIdx.x;
    int u = threadIdx.x;  // 0..63
    const float4* M4 = reinterpret_cast<const float4*>(MB);
    float4 s = make_float4(0.f, 0.f, 0.f, 0.f);
#pragma unroll 4
    for (int t = 0; t < T_DIM; t++) {
        float4 v = M4[((size_t)t * B_DIM + b) * U4 + u];
        s.x += v.x; s.y += v.y; s.z += v.z; s.w += v.w;
    }
    __shared__ float ms;
    if (u == 0) {
        float m = 0.f;
        for (int t = 0; t < T_DIM; t++) m += sent_mask[t * B_DIM + b];
        ms = m;
    }
    __syncthreads();
    float inv = 1.f / ms;
    s.x *= inv; s.y *= inv; s.z *= inv; s.w *= inv;
    reinterpret_cast<float4*>(enc)[b * U4 + u] = s;
}

// ---------------------------------------------------------------------------
// 5) h_all[k,b,w] = sum_u enc[b,u] * H[k,u,w]
// ---------------------------------------------------------------------------
__global__ void hall_k(const float* __restrict__ enc,
                       const float* __restrict__ H,
                       float* __restrict__ out)
{
    int k = blockIdx.y, b = blockIdx.x, w = threadIdx.x;
    __shared__ float es[U_DIM];
    es[w] = enc[b * U_DIM + w];
    __syncthreads();
    const float* Hk = H + (size_t)k * U_DIM * U_DIM;
    float acc = 0.f;
#pragma unroll 8
    for (int u = 0; u < U_DIM; u++)
        acc = fmaf(es[u], Hk[u * U_DIM + w], acc);
    out[((size_t)k * B_DIM + b) * U_DIM + w] = acc;
}

// ---------------------------------------------------------------------------
// Launch
// ---------------------------------------------------------------------------
extern "C" void kernel_launch(void* const* d_in, const int* in_sizes, int n_in,
                              void* d_out, int out_size)
{
    const int*   src       = (const int*)  d_in[0];
    const int*   arc_in    = (const int*)  d_in[1];
    const int*   arc_out   = (const int*)  d_in[2];
    const int*   lab_in    = (const int*)  d_in[3];
    const int*   lab_out   = (const int*)  d_in[4];
    const float* mask_in   = (const float*)d_in[5];
    const float* mask_out  = (const float*)d_in[6];
    const float* mask_loop = (const float*)d_in[7];
    const float* sent_mask = (const float*)d_in[8];
    const float* emb       = (const float*)d_in[9];
    const float* V_in      = (const float*)d_in[10];
    const float* b_in      = (const float*)d_in[11];
    const float* Vg_in     = (const float*)d_in[12];
    const float* bg_in     = (const float*)d_in[13];
    const float* V_out     = (const float*)d_in[14];
    const float* b_out     = (const float*)d_in[15];
    const float* Vg_out    = (const float*)d_in[16];
    const float* bg_out    = (const float*)d_in[17];
    const float* W_loop    = (const float*)d_in[18];
    const float* Wg_loop   = (const float*)d_in[19];
    const float* H         = (const float*)d_in[20];
    float* out = (float*)d_out;

    float *pX0, *pX1, *pXtf, *pWtf, *pXVin, *pXVout, *pXVloop;
    float *pgin, *pgout, *pgloop, *penc;
    cudaGetSymbolAddress((void**)&pX0,     g_X0);
    cudaGetSymbolAddress((void**)&pX1,     g_X1);
    cudaGetSymbolAddress((void**)&pXtf,    g_Xtf);
    cudaGetSymbolAddress((void**)&pWtf,    g_Wtf);
    cudaGetSymbolAddress((void**)&pXVin,   g_XVin);
    cudaGetSymbolAddress((void**)&pXVout,  g_XVout);
    cudaGetSymbolAddress((void**)&pXVloop, g_XVloop);
    cudaGetSymbolAddress((void**)&pgin,    g_gin);
    cudaGetSymbolAddress((void**)&pgout,   g_gout);
    cudaGetSymbolAddress((void**)&pgloop,  g_gloop);
    cudaGetSymbolAddress((void**)&penc,    g_enc);

    cudaFuncSetAttribute(gemm_gate_k,
                         cudaFuncAttributeMaxDynamicSharedMemorySize, SMEM_DYN);

    float* memOut = out + 4 * B_DIM * U_DIM;   // membank region of d_out

    cvtw_k<<<L_LAYERS * 3 * WSZ / 4 / 256, 256>>>(V_in, V_out, W_loop, pWtf);
    embed_k<<<BT / 4, 256>>>(src, emb, pX0, pXtf);

    float* Xcur = pX0;
    for (int l = 0; l < L_LAYERS; l++) {
        const size_t gOff  = (size_t)l * U_DIM;
        const size_t bOff  = (size_t)l * NL_LAB * U_DIM;
        const size_t bgOff = (size_t)l * NL_LAB;
        const int last = (l == L_LAYERS - 1);

        dim3 ggrid(BT / GBM, 7);
        gemm_gate_k<<<ggrid, GTHREADS, SMEM_DYN>>>(
            pXtf, pWtf + (size_t)l * 3 * WSZ,
            pXVin, pXVout, pXVloop,
            Xcur,
            Vg_in + gOff, Vg_out + gOff, Wg_loop + gOff,
            pgin, pgout, pgloop);
        agg_k<<<BT / 4, 256>>>(pXVin, pXVout, pXVloop, pgin, pgout, pgloop,
                               arc_in, arc_out, lab_in, lab_out,
                               b_in + bOff, bg_in + bgOff,
                               b_out + bOff, bg_out + bgOff,
                               mask_in, mask_out, mask_loop, sent_mask,
                               last ? memOut : pX1,
                               last ? nullptr : pXtf,
                               last ? 1 : 0);
        Xcur = pX1;
    }

    enc_k<<<B_DIM, 64>>>(memOut, sent_mask, penc);
    hall_k<<<dim3(B_DIM, 4), U_DIM>>>(penc, H, out);
}